// round 2
// baseline (speedup 1.0000x reference)
#include <cuda_runtime.h>

#define Bb 128
#define Tt 256
#define Hh 512
#define Ee 300
#define Vv 50000
#define FH 2048   // 4*H

// ---------------- scratch (static device globals; no allocs) ----------------
__device__ float g_G0in[(size_t)Tt * Bb * FH];   // precomputed input gates (incl. b0), 256MB
__device__ float g_c0[Bb * Hh];
__device__ float g_c1[Bb * Hh];
__device__ float g_h0[2][Bb * Hh];               // ping-pong
__device__ float g_h1[2][Bb * Hh];               // ping-pong
__device__ int   g_x64;                          // 1 if x is int64, 0 if int32

// ---------------- f32x2 packed-FMA helpers (FFMA2) ----------------
__device__ __forceinline__ unsigned long long pack2(float lo, float hi) {
    unsigned long long r;
    asm("mov.b64 %0, {%1, %2};" : "=l"(r) : "f"(lo), "f"(hi));
    return r;
}
__device__ __forceinline__ void unpack2(unsigned long long v, float& lo, float& hi) {
    asm("mov.b64 {%0, %1}, %2;" : "=f"(lo), "=f"(hi) : "l"(v));
}
__device__ __forceinline__ unsigned long long fma2(unsigned long long a,
                                                   unsigned long long b,
                                                   unsigned long long c) {
    unsigned long long d;
    asm("fma.rn.f32x2 %0, %1, %2, %3;" : "=l"(d) : "l"(a), "l"(b), "l"(c));
    return d;
}

__device__ __forceinline__ float sigm(float x) { return 1.0f / (1.0f + expf(-x)); }

// ---------------- dtype detection for x ----------------
// int32 tokens misread as int64 produce values >= 2^32 with overwhelming
// probability (high word is the next token, ~U[0,50000)). Deterministic.
__global__ void detect_kernel(const void* x) {
    const long long* p = (const long long*)x;
    int ok64 = 1;
    for (int i = 0; i < 16; i++) {
        long long v = p[i];
        if (v < 0 || v >= Vv) ok64 = 0;
    }
    g_x64 = ok64;
}

__device__ __forceinline__ int token_at(const void* x, int idx) {
    if (g_x64) return (int)((const long long*)x)[idx];
    return ((const int*)x)[idx];
}

// ---------------- zero initial state ----------------
__global__ void zero_state_kernel() {
    int i = blockIdx.x * blockDim.x + threadIdx.x;
    if (i < Bb * Hh) {
        g_c0[i] = 0.f; g_c1[i] = 0.f;
        g_h0[0][i] = 0.f; g_h0[1][i] = 0.f;
        g_h1[0][i] = 0.f; g_h1[1][i] = 0.f;
    }
}

// ---------------- precompute: G0in[m, :] = emb[x] @ W0[:300] + b0 ----------------
// m = t*128 + b, M = 32768, N = 2048, K = 300 (= 15 tiles of 20)
// 64x64 tile, 256 threads, 4x4 microtile, FFMA2 pairs along m.
__global__ void __launch_bounds__(256) gemm_in_kernel(
    const void* __restrict__ x, const float* __restrict__ emb,
    const float* __restrict__ W0, const float* __restrict__ b0)
{
    __shared__ __align__(16) float As[20][66];   // [k][m], padded
    __shared__ __align__(16) float Bs[20][64];   // [k][n]
    __shared__ int rows[64];

    int tid = threadIdx.x;
    int n0 = blockIdx.x * 64;
    int m0 = blockIdx.y * 64;

    if (tid < 64) {
        int m = m0 + tid;
        int t = m >> 7;          // m / 128
        int b = m & 127;
        rows[tid] = token_at(x, b * Tt + t);
    }
    __syncthreads();

    int ty = tid >> 4, tx = tid & 15;
    unsigned long long acc[2][4];
#pragma unroll
    for (int i = 0; i < 2; i++)
#pragma unroll
        for (int j = 0; j < 4; j++) acc[i][j] = 0ULL;

    for (int k0 = 0; k0 < Ee; k0 += 20) {
        // A: 20x64 = 1280 elems, 5 per thread
#pragma unroll
        for (int i = 0; i < 5; i++) {
            int idx = i * 256 + tid;
            int k = idx >> 6, m = idx & 63;
            As[k][m] = emb[rows[m] * Ee + k0 + k];
        }
        // B: 20x64, 5 per thread (coalesced)
#pragma unroll
        for (int i = 0; i < 5; i++) {
            int idx = i * 256 + tid;
            int k = idx >> 6, c = idx & 63;
            Bs[k][c] = W0[(k0 + k) * FH + n0 + c];
        }
        __syncthreads();
#pragma unroll
        for (int kk = 0; kk < 20; kk++) {
            float2 a01 = *(const float2*)&As[kk][ty * 4];
            float2 a23 = *(const float2*)&As[kk][ty * 4 + 2];
            float4 b4  = *(const float4*)&Bs[kk][tx * 4];
            unsigned long long ap0 = pack2(a01.x, a01.y);
            unsigned long long ap1 = pack2(a23.x, a23.y);
            unsigned long long bp;
            bp = pack2(b4.x, b4.x); acc[0][0] = fma2(ap0, bp, acc[0][0]); acc[1][0] = fma2(ap1, bp, acc[1][0]);
            bp = pack2(b4.y, b4.y); acc[0][1] = fma2(ap0, bp, acc[0][1]); acc[1][1] = fma2(ap1, bp, acc[1][1]);
            bp = pack2(b4.z, b4.z); acc[0][2] = fma2(ap0, bp, acc[0][2]); acc[1][2] = fma2(ap1, bp, acc[1][2]);
            bp = pack2(b4.w, b4.w); acc[0][3] = fma2(ap0, bp, acc[0][3]); acc[1][3] = fma2(ap1, bp, acc[1][3]);
        }
        __syncthreads();
    }

#pragma unroll
    for (int j = 0; j < 4; j++) {
        int col = n0 + tx * 4 + j;
        float bias = b0[col];
        float v0, v1, v2, v3;
        unpack2(acc[0][j], v0, v1);
        unpack2(acc[1][j], v2, v3);
        size_t base = (size_t)(m0 + ty * 4) * FH + col;
        g_G0in[base]          = v0 + bias;
        g_G0in[base + FH]     = v1 + bias;
        g_G0in[base + 2 * FH] = v2 + bias;
        g_G0in[base + 3 * FH] = v3 + bias;
    }
}

// ---------------- layer-0 step: gates = h0 @ W0[300:] + G0in[t]; update c0,h0 ----------------
// tile: 32 b-rows x 16 cells (64 gate cols: 4 gates x 16), 128 threads, 4x4 microtile.
// grid (4, 32). K = 512, BK = 16.
__global__ void __launch_bounds__(128) step0_kernel(const float* __restrict__ W0, int t, int p)
{
    const float* __restrict__ h_src = g_h0[p];
    float* __restrict__ h_dst = g_h0[1 - p];

    __shared__ __align__(16) float As[16][36];
    __shared__ __align__(16) float Bs[16][64];
    __shared__ float Gs[32][64];

    int tid = threadIdx.x;
    int b0r = blockIdx.x * 32;
    int n0  = blockIdx.y * 16;
    int ty = tid >> 4, tx = tid & 15;

    unsigned long long acc[2][4];
#pragma unroll
    for (int i = 0; i < 2; i++)
#pragma unroll
        for (int j = 0; j < 4; j++) acc[i][j] = 0ULL;

    for (int k0 = 0; k0 < Hh; k0 += 16) {
        // A: 16x32 = 512, 4 per thread, coalesced along k
#pragma unroll
        for (int i = 0; i < 4; i++) {
            int idx = i * 128 + tid;
            int m = idx >> 4, k = idx & 15;
            As[k][m] = h_src[(b0r + m) * Hh + k0 + k];
        }
        // B: 16x64 = 1024, 8 per thread; gate-grouped columns
#pragma unroll
        for (int i = 0; i < 8; i++) {
            int idx = i * 128 + tid;
            int k = idx >> 6, c = idx & 63;
            int col = ((c >> 4) << 9) + n0 + (c & 15);   // gate*512 + n
            Bs[k][c] = W0[(Ee + k0 + k) * FH + col];
        }
        __syncthreads();
#pragma unroll
        for (int kk = 0; kk < 16; kk++) {
            float2 a01 = *(const float2*)&As[kk][ty * 4];
            float2 a23 = *(const float2*)&As[kk][ty * 4 + 2];
            float4 b4  = *(const float4*)&Bs[kk][tx * 4];
            unsigned long long ap0 = pack2(a01.x, a01.y);
            unsigned long long ap1 = pack2(a23.x, a23.y);
            unsigned long long bp;
            bp = pack2(b4.x, b4.x); acc[0][0] = fma2(ap0, bp, acc[0][0]); acc[1][0] = fma2(ap1, bp, acc[1][0]);
            bp = pack2(b4.y, b4.y); acc[0][1] = fma2(ap0, bp, acc[0][1]); acc[1][1] = fma2(ap1, bp, acc[1][1]);
            bp = pack2(b4.z, b4.z); acc[0][2] = fma2(ap0, bp, acc[0][2]); acc[1][2] = fma2(ap1, bp, acc[1][2]);
            bp = pack2(b4.w, b4.w); acc[0][3] = fma2(ap0, bp, acc[0][3]); acc[1][3] = fma2(ap1, bp, acc[1][3]);
        }
        __syncthreads();
    }

    // add precomputed input-gate contributions (already include b0)
#pragma unroll
    for (int j = 0; j < 4; j++) {
        int c = tx * 4 + j;
        int col = ((c >> 4) << 9) + n0 + (c & 15);
        float v0, v1, v2, v3;
        unpack2(acc[0][j], v0, v1);
        unpack2(acc[1][j], v2, v3);
        size_t base = (size_t)(t * Bb + b0r + ty * 4) * FH + col;
        Gs[ty * 4 + 0][c] = v0 + g_G0in[base];
        Gs[ty * 4 + 1][c] = v1 + g_G0in[base + FH];
        Gs[ty * 4 + 2][c] = v2 + g_G0in[base + 2 * FH];
        Gs[ty * 4 + 3][c] = v3 + g_G0in[base + 3 * FH];
    }
    __syncthreads();

    // LSTM cell update: i, j, f, o order; forget_bias = 1
#pragma unroll
    for (int i = 0; i < 4; i++) {
        int idx = i * 128 + tid;
        int m = idx >> 4, n = idx & 15;
        float gi = Gs[m][n], gj = Gs[m][16 + n], gf = Gs[m][32 + n], go = Gs[m][48 + n];
        int ci = (b0r + m) * Hh + n0 + n;
        float c = g_c0[ci];
        float cn = c * sigm(gf + 1.0f) + sigm(gi) * tanhf(gj);
        g_c0[ci] = cn;
        h_dst[ci] = tanhf(cn) * sigm(go);
    }
}

// ---------------- layer-1 step: gates = [h0_cur, h1_prev] @ W1 + b1; update c1,h1 ----------------
__global__ void __launch_bounds__(128) step1_kernel(const float* __restrict__ W1,
                                                    const float* __restrict__ b1, int p)
{
    const float* __restrict__ h0cur  = g_h0[1 - p];
    const float* __restrict__ h1prev = g_h1[p];
    float* __restrict__ h_dst = g_h1[1 - p];

    __shared__ __align__(16) float As[16][36];
    __shared__ __align__(16) float Bs[16][64];
    __shared__ float Gs[32][64];

    int tid = threadIdx.x;
    int b0r = blockIdx.x * 32;
    int n0  = blockIdx.y * 16;
    int ty = tid >> 4, tx = tid & 15;

    unsigned long long acc[2][4];
#pragma unroll
    for (int i = 0; i < 2; i++)
#pragma unroll
        for (int j = 0; j < 4; j++) acc[i][j] = 0ULL;

    for (int k0 = 0; k0 < 2 * Hh; k0 += 16) {
        const float* __restrict__ src = (k0 < Hh) ? h0cur : h1prev;
        int koff = (k0 < Hh) ? k0 : (k0 - Hh);
#pragma unroll
        for (int i = 0; i < 4; i++) {
            int idx = i * 128 + tid;
            int m = idx >> 4, k = idx & 15;
            As[k][m] = src[(b0r + m) * Hh + koff + k];
        }
#pragma unroll
        for (int i = 0; i < 8; i++) {
            int idx = i * 128 + tid;
            int k = idx >> 6, c = idx & 63;
            int col = ((c >> 4) << 9) + n0 + (c & 15);
            Bs[k][c] = W1[(k0 + k) * FH + col];
        }
        __syncthreads();
#pragma unroll
        for (int kk = 0; kk < 16; kk++) {
            float2 a01 = *(const float2*)&As[kk][ty * 4];
            float2 a23 = *(const float2*)&As[kk][ty * 4 + 2];
            float4 b4  = *(const float4*)&Bs[kk][tx * 4];
            unsigned long long ap0 = pack2(a01.x, a01.y);
            unsigned long long ap1 = pack2(a23.x, a23.y);
            unsigned long long bp;
            bp = pack2(b4.x, b4.x); acc[0][0] = fma2(ap0, bp, acc[0][0]); acc[1][0] = fma2(ap1, bp, acc[1][0]);
            bp = pack2(b4.y, b4.y); acc[0][1] = fma2(ap0, bp, acc[0][1]); acc[1][1] = fma2(ap1, bp, acc[1][1]);
            bp = pack2(b4.z, b4.z); acc[0][2] = fma2(ap0, bp, acc[0][2]); acc[1][2] = fma2(ap1, bp, acc[1][2]);
            bp = pack2(b4.w, b4.w); acc[0][3] = fma2(ap0, bp, acc[0][3]); acc[1][3] = fma2(ap1, bp, acc[1][3]);
        }
        __syncthreads();
    }

#pragma unroll
    for (int j = 0; j < 4; j++) {
        int c = tx * 4 + j;
        int col = ((c >> 4) << 9) + n0 + (c & 15);
        float bias = b1[col];
        float v0, v1, v2, v3;
        unpack2(acc[0][j], v0, v1);
        unpack2(acc[1][j], v2, v3);
        Gs[ty * 4 + 0][c] = v0 + bias;
        Gs[ty * 4 + 1][c] = v1 + bias;
        Gs[ty * 4 + 2][c] = v2 + bias;
        Gs[ty * 4 + 3][c] = v3 + bias;
    }
    __syncthreads();

#pragma unroll
    for (int i = 0; i < 4; i++) {
        int idx = i * 128 + tid;
        int m = idx >> 4, n = idx & 15;
        float gi = Gs[m][n], gj = Gs[m][16 + n], gf = Gs[m][32 + n], go = Gs[m][48 + n];
        int ci = (b0r + m) * Hh + n0 + n;
        float c = g_c1[ci];
        float cn = c * sigm(gf + 1.0f) + sigm(gi) * tanhf(gj);
        g_c1[ci] = cn;
        h_dst[ci] = tanhf(cn) * sigm(go);
    }
}

// ---------------- logits = h1_final @ Wd + bd ----------------
// T=256 is even, so the final h1 lives in buffer 0.
__global__ void final_kernel(const float* __restrict__ Wd, const float* __restrict__ bd,
                             float* __restrict__ out)
{
    int tid = threadIdx.x;      // 256 threads: (b, o)
    int b = tid >> 1, o = tid & 1;
    const float* h = g_h1[0];
    float s = bd[o];
    for (int n = 0; n < Hh; n++) s += h[b * Hh + n] * Wd[n * 2 + o];
    out[b * 2 + o] = s;
}

// ---------------- launch ----------------
extern "C" void kernel_launch(void* const* d_in, const int* in_sizes, int n_in,
                              void* d_out, int out_size)
{
    const void*  x   = d_in[0];
    const float* emb = (const float*)d_in[1];
    const float* W0  = (const float*)d_in[2];
    const float* b0  = (const float*)d_in[3];
    const float* W1  = (const float*)d_in[4];
    const float* b1  = (const float*)d_in[5];
    const float* Wd  = (const float*)d_in[6];
    const float* bd  = (const float*)d_in[7];
    float* out = (float*)d_out;
    (void)in_sizes; (void)n_in; (void)out_size;

    detect_kernel<<<1, 1>>>(x);
    zero_state_kernel<<<256, 256>>>();

    dim3 gp(FH / 64, (Bb * Tt) / 64);        // (32, 512)
    gemm_in_kernel<<<gp, 256>>>(x, emb, W0, b0);

    for (int t = 0; t < Tt; t++) {
        int p = t & 1;
        step0_kernel<<<dim3(4, 32), 128>>>(W0, t, p);
        step1_kernel<<<dim3(4, 32), 128>>>(W1, b1, p);
    }
    final_kernel<<<1, 256>>>(Wd, bd, out);
}

// round 3
// speedup vs baseline: 1.6124x; 1.6124x over previous
#include <cuda_runtime.h>

#define Bb 128
#define Tt 256
#define Hh 512
#define Ee 300
#define Vv 50000
#define FH 2048   // 4*H
#define NCTA 128

// ---------------- scratch (static device globals; no allocs) ----------------
__device__ float g_G0in[(size_t)Tt * FH * Bb];   // [t][col][b] transposed, 256MB
__device__ float g_h0[2][Hh * Bb];               // transposed [cell][row], ping-pong
__device__ float g_h1[2][Hh * Bb];
__device__ int   g_x64;
__device__ unsigned g_bar_arrive;
__device__ volatile unsigned g_bar_gen;

// ---------------- f32x2 packed-FMA helpers ----------------
__device__ __forceinline__ unsigned long long pack2(float lo, float hi) {
    unsigned long long r;
    asm("mov.b64 %0, {%1, %2};" : "=l"(r) : "f"(lo), "f"(hi));
    return r;
}
__device__ __forceinline__ void unpack2(unsigned long long v, float& lo, float& hi) {
    asm("mov.b64 {%0, %1}, %2;" : "=f"(lo), "=f"(hi) : "l"(v));
}
__device__ __forceinline__ unsigned long long fma2(unsigned long long a,
                                                   unsigned long long b,
                                                   unsigned long long c) {
    unsigned long long d;
    asm("fma.rn.f32x2 %0, %1, %2, %3;" : "=l"(d) : "l"(a), "l"(b), "l"(c));
    return d;
}

__device__ __forceinline__ float ex2f(float x) { float y; asm("ex2.approx.f32 %0, %1;" : "=f"(y) : "f"(x)); return y; }
__device__ __forceinline__ float rcpf(float x) { float y; asm("rcp.approx.f32 %0, %1;" : "=f"(y) : "f"(x)); return y; }
__device__ __forceinline__ float sigm(float x) { return rcpf(1.0f + ex2f(-1.4426950408889634f * x)); }
__device__ __forceinline__ float tanh_(float x) { return fmaf(2.0f, sigm(2.0f * x), -1.0f); }

// ---------------- grid barrier (gen-based) ----------------
__device__ __forceinline__ void grid_sync() {
    __syncthreads();
    if (threadIdx.x == 0) {
        unsigned gen = g_bar_gen;
        __threadfence();
        if (atomicAdd(&g_bar_arrive, 1u) == NCTA - 1) {
            g_bar_arrive = 0;
            __threadfence();
            g_bar_gen = gen + 1;
        } else {
            while (g_bar_gen == gen) { }
        }
        __threadfence();
    }
    __syncthreads();
}

// ---------------- dtype detection for x ----------------
__global__ void detect_kernel(const void* x) {
    const long long* p = (const long long*)x;
    int ok64 = 1;
    for (int i = 0; i < 16; i++) {
        long long v = p[i];
        if (v < 0 || v >= Vv) ok64 = 0;
    }
    g_x64 = ok64;
}

__device__ __forceinline__ int token_at(const void* x, int idx) {
    if (g_x64) return (int)((const long long*)x)[idx];
    return ((const int*)x)[idx];
}

__global__ void reset_kernel() { g_bar_arrive = 0; g_bar_gen = 0; }

// ---------------- precompute: G0in_t[t][col][b] = (emb[x] @ W0[:300])^T + b0 ----------------
__global__ void __launch_bounds__(256) gemm_in_kernel(
    const void* __restrict__ x, const float* __restrict__ emb,
    const float* __restrict__ W0, const float* __restrict__ b0)
{
    __shared__ __align__(16) float As[20][66];   // [k][m]
    __shared__ __align__(16) float Bs[20][64];   // [k][n]
    __shared__ float Gs[64][65];                 // [col][m] transpose buffer
    __shared__ int rows[64];

    int tid = threadIdx.x;
    int n0 = blockIdx.x * 64;
    int m0 = blockIdx.y * 64;

    if (tid < 64) {
        int m = m0 + tid;
        int t = m >> 7;
        int b = m & 127;
        rows[tid] = token_at(x, b * Tt + t);
    }
    __syncthreads();

    int ty = tid >> 4, tx = tid & 15;
    unsigned long long acc[2][4];
#pragma unroll
    for (int i = 0; i < 2; i++)
#pragma unroll
        for (int j = 0; j < 4; j++) acc[i][j] = 0ULL;

    for (int k0 = 0; k0 < Ee; k0 += 20) {
#pragma unroll
        for (int i = 0; i < 5; i++) {
            int idx = i * 256 + tid;
            int k = idx >> 6, m = idx & 63;
            As[k][m] = emb[rows[m] * Ee + k0 + k];
        }
#pragma unroll
        for (int i = 0; i < 5; i++) {
            int idx = i * 256 + tid;
            int k = idx >> 6, c = idx & 63;
            Bs[k][c] = W0[(k0 + k) * FH + n0 + c];
        }
        __syncthreads();
#pragma unroll
        for (int kk = 0; kk < 20; kk++) {
            float2 a01 = *(const float2*)&As[kk][ty * 4];
            float2 a23 = *(const float2*)&As[kk][ty * 4 + 2];
            float4 b4  = *(const float4*)&Bs[kk][tx * 4];
            unsigned long long ap0 = pack2(a01.x, a01.y);
            unsigned long long ap1 = pack2(a23.x, a23.y);
            unsigned long long bp;
            bp = pack2(b4.x, b4.x); acc[0][0] = fma2(ap0, bp, acc[0][0]); acc[1][0] = fma2(ap1, bp, acc[1][0]);
            bp = pack2(b4.y, b4.y); acc[0][1] = fma2(ap0, bp, acc[0][1]); acc[1][1] = fma2(ap1, bp, acc[1][1]);
            bp = pack2(b4.z, b4.z); acc[0][2] = fma2(ap0, bp, acc[0][2]); acc[1][2] = fma2(ap1, bp, acc[1][2]);
            bp = pack2(b4.w, b4.w); acc[0][3] = fma2(ap0, bp, acc[0][3]); acc[1][3] = fma2(ap1, bp, acc[1][3]);
        }
        __syncthreads();
    }

    // transpose into Gs[col][m] with bias added
#pragma unroll
    for (int j = 0; j < 4; j++) {
        int c = tx * 4 + j;
        float bias = b0[n0 + c];
        float v0, v1, v2, v3;
        unpack2(acc[0][j], v0, v1);
        unpack2(acc[1][j], v2, v3);
        Gs[c][ty * 4 + 0] = v0 + bias;
        Gs[c][ty * 4 + 1] = v1 + bias;
        Gs[c][ty * 4 + 2] = v2 + bias;
        Gs[c][ty * 4 + 3] = v3 + bias;
    }
    __syncthreads();

    int tblk = m0 >> 7;
    int bbase = m0 & 127;
#pragma unroll
    for (int i = 0; i < 16; i++) {
        int e = i * 256 + tid;
        int c = e >> 6, m = e & 63;
        g_G0in[((size_t)tblk * FH + n0 + c) * Bb + bbase + m] = Gs[c][m];
    }
}

// ---------------- GEMM inner: one kgroup, streams h tiles, accumulates 4r x 4c ----------------
__device__ __forceinline__ void gemm_part(
    const float4* __restrict__ src4,     // [k][128] floats as float4, this kgroup's range
    const float* __restrict__ wsm,       // smem weights, stride 16, this kgroup's range
    float* __restrict__ tb,              // this kgroup's 2 tile buffers (each 4224 floats)
    int ntiles, int t7, int rg4, int ct4,
    unsigned long long* __restrict__ acc)
{
    float4 ld[8];
#pragma unroll
    for (int j = 0; j < 8; j++) ld[j] = __ldcg(&src4[j * 128 + t7]);
#pragma unroll
    for (int j = 0; j < 8; j++) {
        int e = j * 128 + t7;
        int k = e >> 5, r4 = (e & 31) << 2;
        *(float4*)&tb[k * 132 + r4] = ld[j];
    }
    __syncthreads();

    for (int kt = 0; kt < ntiles; kt++) {
        const float* cur = tb + (kt & 1) * 4224;
        bool more = (kt + 1 < ntiles);
        if (more) {
#pragma unroll
            for (int j = 0; j < 8; j++) ld[j] = __ldcg(&src4[(kt + 1) * 1024 + j * 128 + t7]);
        }
        const float* wk = wsm + kt * 512 + ct4;
#pragma unroll
        for (int k = 0; k < 32; k++) {
            float4 hv = *(const float4*)&cur[k * 132 + rg4];
            float4 wv = *(const float4*)&wk[k * 16];
            unsigned long long h01 = pack2(hv.x, hv.y);
            unsigned long long h23 = pack2(hv.z, hv.w);
            unsigned long long w;
            w = pack2(wv.x, wv.x); acc[0] = fma2(h01, w, acc[0]); acc[1] = fma2(h23, w, acc[1]);
            w = pack2(wv.y, wv.y); acc[2] = fma2(h01, w, acc[2]); acc[3] = fma2(h23, w, acc[3]);
            w = pack2(wv.z, wv.z); acc[4] = fma2(h01, w, acc[4]); acc[5] = fma2(h23, w, acc[5]);
            w = pack2(wv.w, wv.w); acc[6] = fma2(h01, w, acc[6]); acc[7] = fma2(h23, w, acc[7]);
        }
        if (more) {
            float* nxt = tb + ((kt + 1) & 1) * 4224;
#pragma unroll
            for (int j = 0; j < 8; j++) {
                int e = j * 128 + t7;
                int k = e >> 5, r4 = (e & 31) << 2;
                *(float4*)&nxt[k * 132 + r4] = ld[j];
            }
        }
        __syncthreads();
    }
}

// ---------------- persistent LSTM kernel ----------------
// SMEM layout (floats):
//  w0s   [0,      8192)   512 x 16
//  w1s   [8192,  24576)  1024 x 16
//  tiles [24576, 41472)   4 x 32 x 132
//  gsum  [41472, 45696)   2 x 16 x 132
//  c0s   [45696, 46208)
//  c1s   [46208, 46720)
//  bias1 [46720, 46736)
#define SMEM_FLOATS 46736

__global__ void __launch_bounds__(256, 1) lstm_persist(
    const float* __restrict__ W0, const float* __restrict__ W1,
    const float* __restrict__ b1, const float* __restrict__ Wd,
    const float* __restrict__ bd, float* __restrict__ out)
{
    extern __shared__ float sm[];
    float* w0s   = sm;
    float* w1s   = sm + 8192;
    float* tiles = sm + 24576;
    float* gsum  = sm + 41472;
    float* c0s   = sm + 45696;
    float* c1s   = sm + 46208;
    float* bias1 = sm + 46720;

    const int tid   = threadIdx.x;
    const int cta   = blockIdx.x;
    const int cell0 = cta * 4;

    // ---- one-time weight preload (resident for all 256 steps) ----
    for (int i = tid; i < 2048; i += 256) {         // (k=512) x (g=4)
        int k = i >> 2, g = i & 3;
        *(float4*)&w0s[k * 16 + g * 4] = *(const float4*)&W0[(size_t)(Ee + k) * FH + g * 512 + cell0];
    }
    for (int i = tid; i < 4096; i += 256) {         // (k=1024) x (g=4)
        int k = i >> 2, g = i & 3;
        *(float4*)&w1s[k * 16 + g * 4] = *(const float4*)&W1[(size_t)k * FH + g * 512 + cell0];
    }
    if (tid < 16) bias1[tid] = b1[(tid >> 2) * 512 + cell0 + (tid & 3)];
    for (int i = tid; i < 512; i += 256) {
        c0s[i] = 0.f; c1s[i] = 0.f;
        g_h0[0][cell0 * 128 + i] = 0.f;
        g_h1[0][cell0 * 128 + i] = 0.f;
    }
    grid_sync();

    const int kg  = tid >> 7;
    const int t7  = tid & 127;
    const int rg4 = (t7 >> 2) << 2;     // rows rg4..rg4+3
    const int ct4 = (t7 & 3) << 2;      // local cols ct4..ct4+3
    float* tb = tiles + kg * 8448;

    // epilogue mapping: update u=0 -> (row0, cl0), u=1 -> (row0, cl0+2)
    const int row0 = tid & 127;
    const int cl0  = tid >> 7;
    const int cl1  = cl0 + 2;

    for (int t = 0; t < Tt; t++) {
        const int p = t & 1;

        // prefetch G0in for epilogue (hidden under GEMM)
        float g0a[4], g0b[4];
        {
            size_t base = (size_t)t * FH * Bb;
#pragma unroll
            for (int g = 0; g < 4; g++) {
                g0a[g] = g_G0in[base + (size_t)(g * 512 + cell0 + cl0) * Bb + row0];
                g0b[g] = g_G0in[base + (size_t)(g * 512 + cell0 + cl1) * Bb + row0];
            }
        }

        // ---- phase 1: layer-0 recurrent GEMM + cell update ----
        unsigned long long acc[8];
#pragma unroll
        for (int i = 0; i < 8; i++) acc[i] = 0ULL;
        gemm_part((const float4*)(g_h0[p] + kg * 256 * 128), w0s + kg * 4096, tb, 8,
                  t7, rg4, ct4, acc);
#pragma unroll
        for (int c = 0; c < 4; c++) {
            float4 v;
            unpack2(acc[c * 2],     v.x, v.y);
            unpack2(acc[c * 2 + 1], v.z, v.w);
            *(float4*)&gsum[(kg * 16 + ct4 + c) * 132 + rg4] = v;
        }
        __syncthreads();
        {
            float* hdst = g_h0[1 - p];
            float gi = gsum[(0  + cl0) * 132 + row0] + gsum[(16 + cl0) * 132 + row0] + g0a[0];
            float gj = gsum[(4  + cl0) * 132 + row0] + gsum[(20 + cl0) * 132 + row0] + g0a[1];
            float gf = gsum[(8  + cl0) * 132 + row0] + gsum[(24 + cl0) * 132 + row0] + g0a[2];
            float go = gsum[(12 + cl0) * 132 + row0] + gsum[(28 + cl0) * 132 + row0] + g0a[3];
            float c  = c0s[cl0 * 128 + row0];
            float cn = c * sigm(gf + 1.0f) + sigm(gi) * tanh_(gj);
            c0s[cl0 * 128 + row0] = cn;
            hdst[(cell0 + cl0) * 128 + row0] = tanh_(cn) * sigm(go);

            gi = gsum[(0  + cl1) * 132 + row0] + gsum[(16 + cl1) * 132 + row0] + g0b[0];
            gj = gsum[(4  + cl1) * 132 + row0] + gsum[(20 + cl1) * 132 + row0] + g0b[1];
            gf = gsum[(8  + cl1) * 132 + row0] + gsum[(24 + cl1) * 132 + row0] + g0b[2];
            go = gsum[(12 + cl1) * 132 + row0] + gsum[(28 + cl1) * 132 + row0] + g0b[3];
            c  = c1s[0]; // placeholder to keep symmetry? no:
            c  = c0s[cl1 * 128 + row0];
            cn = c * sigm(gf + 1.0f) + sigm(gi) * tanh_(gj);
            c0s[cl1 * 128 + row0] = cn;
            hdst[(cell0 + cl1) * 128 + row0] = tanh_(cn) * sigm(go);
        }
        grid_sync();

        // ---- phase 2: layer-1 GEMM over [h0_cur ; h1_prev] + cell update ----
#pragma unroll
        for (int i = 0; i < 8; i++) acc[i] = 0ULL;
        const float* hsrc2 = (kg == 0) ? g_h0[1 - p] : g_h1[p];
        gemm_part((const float4*)hsrc2, w1s + kg * 8192, tb, 16, t7, rg4, ct4, acc);
#pragma unroll
        for (int c = 0; c < 4; c++) {
            float4 v;
            unpack2(acc[c * 2],     v.x, v.y);
            unpack2(acc[c * 2 + 1], v.z, v.w);
            *(float4*)&gsum[(kg * 16 + ct4 + c) * 132 + rg4] = v;
        }
        __syncthreads();
        {
            float* hdst = g_h1[1 - p];
            float gi = gsum[(0  + cl0) * 132 + row0] + gsum[(16 + cl0) * 132 + row0] + bias1[0  + cl0];
            float gj = gsum[(4  + cl0) * 132 + row0] + gsum[(20 + cl0) * 132 + row0] + bias1[4  + cl0];
            float gf = gsum[(8  + cl0) * 132 + row0] + gsum[(24 + cl0) * 132 + row0] + bias1[8  + cl0];
            float go = gsum[(12 + cl0) * 132 + row0] + gsum[(28 + cl0) * 132 + row0] + bias1[12 + cl0];
            float c  = c1s[cl0 * 128 + row0];
            float cn = c * sigm(gf + 1.0f) + sigm(gi) * tanh_(gj);
            c1s[cl0 * 128 + row0] = cn;
            hdst[(cell0 + cl0) * 128 + row0] = tanh_(cn) * sigm(go);

            gi = gsum[(0  + cl1) * 132 + row0] + gsum[(16 + cl1) * 132 + row0] + bias1[0  + cl1];
            gj = gsum[(4  + cl1) * 132 + row0] + gsum[(20 + cl1) * 132 + row0] + bias1[4  + cl1];
            gf = gsum[(8  + cl1) * 132 + row0] + gsum[(24 + cl1) * 132 + row0] + bias1[8  + cl1];
            go = gsum[(12 + cl1) * 132 + row0] + gsum[(28 + cl1) * 132 + row0] + bias1[12 + cl1];
            c  = c1s[cl1 * 128 + row0];
            cn = c * sigm(gf + 1.0f) + sigm(gi) * tanh_(gj);
            c1s[cl1 * 128 + row0] = cn;
            hdst[(cell0 + cl1) * 128 + row0] = tanh_(cn) * sigm(go);
        }
        grid_sync();
    }

    // ---- final logits: CTA b computes out[b][0..1]; final h1 is buffer 0 ----
    {
        int b = cta;
        float s0 = 0.f, s1 = 0.f;
        for (int n = tid; n < Hh; n += 256) {
            float h = __ldcg(&g_h1[0][n * 128 + b]);
            s0 += h * Wd[n * 2];
            s1 += h * Wd[n * 2 + 1];
        }
        gsum[tid] = s0;
        gsum[256 + tid] = s1;
        __syncthreads();
        for (int s = 128; s > 0; s >>= 1) {
            if (tid < s) {
                gsum[tid] += gsum[tid + s];
                gsum[256 + tid] += gsum[256 + tid + s];
            }
            __syncthreads();
        }
        if (tid == 0) {
            out[b * 2]     = gsum[0]   + bd[0];
            out[b * 2 + 1] = gsum[256] + bd[1];
        }
    }
}

// ---------------- launch ----------------
extern "C" void kernel_launch(void* const* d_in, const int* in_sizes, int n_in,
                              void* d_out, int out_size)
{
    const void*  x   = d_in[0];
    const float* emb = (const float*)d_in[1];
    const float* W0  = (const float*)d_in[2];
    const float* b0  = (const float*)d_in[3];
    const float* W1  = (const float*)d_in[4];
    const float* b1  = (const float*)d_in[5];
    const float* Wd  = (const float*)d_in[6];
    const float* bd  = (const float*)d_in[7];
    float* out = (float*)d_out;
    (void)in_sizes; (void)n_in; (void)out_size;

    static int smem_set = 0;
    if (!smem_set) {
        cudaFuncSetAttribute(lstm_persist, cudaFuncAttributeMaxDynamicSharedMemorySize,
                             SMEM_FLOATS * sizeof(float));
        smem_set = 1;
    }

    detect_kernel<<<1, 1>>>(x);
    reset_kernel<<<1, 1>>>();

    dim3 gp(FH / 64, (Bb * Tt) / 64);        // (32, 512)
    gemm_in_kernel<<<gp, 256>>>(x, emb, W0, b0);

    lstm_persist<<<NCTA, 256, SMEM_FLOATS * sizeof(float)>>>(W0, W1, b1, Wd, bd, out);
}

// round 4
// speedup vs baseline: 1.6887x; 1.0473x over previous
#include <cuda_runtime.h>

#define Bb 128
#define Tt 256
#define Hh 512
#define Ee 300
#define Vv 50000
#define FH 2048   // 4*H
#define NCTA 128

// ---------------- scratch (static device globals; no allocs) ----------------
__device__ float g_G0in[(size_t)Tt * FH * Bb];   // [t][col][b] transposed, 256MB
__device__ float g_h0[2][Hh * Bb];               // transposed [cell][row], ping-pong
__device__ float g_h1[2][Hh * Bb];
__device__ int   g_x64;
__device__ unsigned g_bar_arrive;
__device__ volatile unsigned g_bar_gen;

// ---------------- f32x2 packed-FMA helpers ----------------
__device__ __forceinline__ unsigned long long pack2(float lo, float hi) {
    unsigned long long r;
    asm("mov.b64 %0, {%1, %2};" : "=l"(r) : "f"(lo), "f"(hi));
    return r;
}
__device__ __forceinline__ void unpack2(unsigned long long v, float& lo, float& hi) {
    asm("mov.b64 {%0, %1}, %2;" : "=f"(lo), "=f"(hi) : "l"(v));
}
__device__ __forceinline__ unsigned long long fma2(unsigned long long a,
                                                   unsigned long long b,
                                                   unsigned long long c) {
    unsigned long long d;
    asm("fma.rn.f32x2 %0, %1, %2, %3;" : "=l"(d) : "l"(a), "l"(b), "l"(c));
    return d;
}

__device__ __forceinline__ float ex2f(float x) { float y; asm("ex2.approx.f32 %0, %1;" : "=f"(y) : "f"(x)); return y; }
__device__ __forceinline__ float rcpf(float x) { float y; asm("rcp.approx.f32 %0, %1;" : "=f"(y) : "f"(x)); return y; }
__device__ __forceinline__ float sigm(float x) { return rcpf(1.0f + ex2f(-1.4426950408889634f * x)); }
__device__ __forceinline__ float tanh_(float x) { return fmaf(2.0f, sigm(2.0f * x), -1.0f); }

// ---------------- grid barrier (gen-based) ----------------
__device__ __forceinline__ void grid_sync() {
    __syncthreads();
    if (threadIdx.x == 0) {
        unsigned gen = g_bar_gen;
        __threadfence();
        if (atomicAdd(&g_bar_arrive, 1u) == NCTA - 1) {
            g_bar_arrive = 0;
            __threadfence();
            g_bar_gen = gen + 1;
        } else {
            while (g_bar_gen == gen) { }
        }
        __threadfence();
    }
    __syncthreads();
}

// ---------------- dtype detection for x ----------------
__global__ void detect_kernel(const void* x) {
    const long long* p = (const long long*)x;
    int ok64 = 1;
    for (int i = 0; i < 16; i++) {
        long long v = p[i];
        if (v < 0 || v >= Vv) ok64 = 0;
    }
    g_x64 = ok64;
}

__device__ __forceinline__ int token_at(const void* x, int idx) {
    if (g_x64) return (int)((const long long*)x)[idx];
    return ((const int*)x)[idx];
}

__global__ void reset_kernel() { g_bar_arrive = 0; g_bar_gen = 0; }

// ---------------- precompute: G0in_t[t][col][b] = (emb[x] @ W0[:300])^T + b0 ----------------
__global__ void __launch_bounds__(256) gemm_in_kernel(
    const void* __restrict__ x, const float* __restrict__ emb,
    const float* __restrict__ W0, const float* __restrict__ b0)
{
    __shared__ __align__(16) float As[20][66];   // [k][m]
    __shared__ __align__(16) float Bs[20][64];   // [k][n]
    __shared__ float Gs[64][65];                 // [col][m] transpose buffer
    __shared__ int rows[64];

    int tid = threadIdx.x;
    int n0 = blockIdx.x * 64;
    int m0 = blockIdx.y * 64;

    if (tid < 64) {
        int m = m0 + tid;
        int t = m >> 7;
        int b = m & 127;
        rows[tid] = token_at(x, b * Tt + t);
    }
    __syncthreads();

    int ty = tid >> 4, tx = tid & 15;
    unsigned long long acc[2][4];
#pragma unroll
    for (int i = 0; i < 2; i++)
#pragma unroll
        for (int j = 0; j < 4; j++) acc[i][j] = 0ULL;

    for (int k0 = 0; k0 < Ee; k0 += 20) {
#pragma unroll
        for (int i = 0; i < 5; i++) {
            int idx = i * 256 + tid;
            int k = idx >> 6, m = idx & 63;
            As[k][m] = emb[rows[m] * Ee + k0 + k];
        }
#pragma unroll
        for (int i = 0; i < 5; i++) {
            int idx = i * 256 + tid;
            int k = idx >> 6, c = idx & 63;
            Bs[k][c] = W0[(k0 + k) * FH + n0 + c];
        }
        __syncthreads();
#pragma unroll
        for (int kk = 0; kk < 20; kk++) {
            float2 a01 = *(const float2*)&As[kk][ty * 4];
            float2 a23 = *(const float2*)&As[kk][ty * 4 + 2];
            float4 b4  = *(const float4*)&Bs[kk][tx * 4];
            unsigned long long ap0 = pack2(a01.x, a01.y);
            unsigned long long ap1 = pack2(a23.x, a23.y);
            unsigned long long bp;
            bp = pack2(b4.x, b4.x); acc[0][0] = fma2(ap0, bp, acc[0][0]); acc[1][0] = fma2(ap1, bp, acc[1][0]);
            bp = pack2(b4.y, b4.y); acc[0][1] = fma2(ap0, bp, acc[0][1]); acc[1][1] = fma2(ap1, bp, acc[1][1]);
            bp = pack2(b4.z, b4.z); acc[0][2] = fma2(ap0, bp, acc[0][2]); acc[1][2] = fma2(ap1, bp, acc[1][2]);
            bp = pack2(b4.w, b4.w); acc[0][3] = fma2(ap0, bp, acc[0][3]); acc[1][3] = fma2(ap1, bp, acc[1][3]);
        }
        __syncthreads();
    }

    // transpose into Gs[col][m] with bias added
#pragma unroll
    for (int j = 0; j < 4; j++) {
        int c = tx * 4 + j;
        float bias = b0[n0 + c];
        float v0, v1, v2, v3;
        unpack2(acc[0][j], v0, v1);
        unpack2(acc[1][j], v2, v3);
        Gs[c][ty * 4 + 0] = v0 + bias;
        Gs[c][ty * 4 + 1] = v1 + bias;
        Gs[c][ty * 4 + 2] = v2 + bias;
        Gs[c][ty * 4 + 3] = v3 + bias;
    }
    __syncthreads();

    int tblk = m0 >> 7;
    int bbase = m0 & 127;
#pragma unroll
    for (int i = 0; i < 16; i++) {
        int e = i * 256 + tid;
        int c = e >> 6, m = e & 63;
        g_G0in[((size_t)tblk * FH + n0 + c) * Bb + bbase + m] = Gs[c][m];
    }
}

// ---------------- GEMM inner: one kgroup, streams h tiles, accumulates 4r x 4c ----------------
__device__ __forceinline__ void gemm_part(
    const float4* __restrict__ src4,     // [k][128] floats as float4, this kgroup's range
    const float* __restrict__ wsm,       // smem weights, stride 16, this kgroup's range
    float* __restrict__ tb,              // this kgroup's 2 tile buffers (each 4224 floats)
    int ntiles, int t7, int rg4, int ct4,
    unsigned long long* __restrict__ acc)
{
    float4 ld[8];
#pragma unroll
    for (int j = 0; j < 8; j++) ld[j] = __ldcg(&src4[j * 128 + t7]);
#pragma unroll
    for (int j = 0; j < 8; j++) {
        int e = j * 128 + t7;
        int k = e >> 5, r4 = (e & 31) << 2;
        *(float4*)&tb[k * 132 + r4] = ld[j];
    }
    __syncthreads();

    for (int kt = 0; kt < ntiles; kt++) {
        const float* cur = tb + (kt & 1) * 4224;
        bool more = (kt + 1 < ntiles);
        if (more) {
#pragma unroll
            for (int j = 0; j < 8; j++) ld[j] = __ldcg(&src4[(kt + 1) * 1024 + j * 128 + t7]);
        }
        const float* wk = wsm + kt * 512 + ct4;
#pragma unroll
        for (int k = 0; k < 32; k++) {
            float4 hv = *(const float4*)&cur[k * 132 + rg4];
            float4 wv = *(const float4*)&wk[k * 16];
            unsigned long long h01 = pack2(hv.x, hv.y);
            unsigned long long h23 = pack2(hv.z, hv.w);
            unsigned long long w;
            w = pack2(wv.x, wv.x); acc[0] = fma2(h01, w, acc[0]); acc[1] = fma2(h23, w, acc[1]);
            w = pack2(wv.y, wv.y); acc[2] = fma2(h01, w, acc[2]); acc[3] = fma2(h23, w, acc[3]);
            w = pack2(wv.z, wv.z); acc[4] = fma2(h01, w, acc[4]); acc[5] = fma2(h23, w, acc[5]);
            w = pack2(wv.w, wv.w); acc[6] = fma2(h01, w, acc[6]); acc[7] = fma2(h23, w, acc[7]);
        }
        if (more) {
            float* nxt = tb + ((kt + 1) & 1) * 4224;
#pragma unroll
            for (int j = 0; j < 8; j++) {
                int e = j * 128 + t7;
                int k = e >> 5, r4 = (e & 31) << 2;
                *(float4*)&nxt[k * 132 + r4] = ld[j];
            }
        }
        __syncthreads();
    }
}

// ---------------- persistent LSTM kernel ----------------
// SMEM layout (floats):
//  w0s   [0,      8192)   512 x 16
//  w1s   [8192,  24576)  1024 x 16
//  tiles [24576, 41472)   4 x 32 x 132
//  gsum  [41472, 45696)   2 x 16 x 132
//  c0s   [45696, 46208)
//  c1s   [46208, 46720)
//  bias1 [46720, 46736)
#define SMEM_FLOATS 46736

__global__ void __launch_bounds__(256, 1) lstm_persist(
    const float* __restrict__ W0, const float* __restrict__ W1,
    const float* __restrict__ b1, const float* __restrict__ Wd,
    const float* __restrict__ bd, float* __restrict__ out)
{
    extern __shared__ float sm[];
    float* w0s   = sm;
    float* w1s   = sm + 8192;
    float* tiles = sm + 24576;
    float* gsum  = sm + 41472;
    float* c0s   = sm + 45696;
    float* c1s   = sm + 46208;
    float* bias1 = sm + 46720;

    const int tid   = threadIdx.x;
    const int cta   = blockIdx.x;
    const int cell0 = cta * 4;

    // ---- one-time weight preload (resident for all 256 steps) ----
    for (int i = tid; i < 2048; i += 256) {         // (k=512) x (g=4)
        int k = i >> 2, g = i & 3;
        *(float4*)&w0s[k * 16 + g * 4] = *(const float4*)&W0[(size_t)(Ee + k) * FH + g * 512 + cell0];
    }
    for (int i = tid; i < 4096; i += 256) {         // (k=1024) x (g=4)
        int k = i >> 2, g = i & 3;
        *(float4*)&w1s[k * 16 + g * 4] = *(const float4*)&W1[(size_t)k * FH + g * 512 + cell0];
    }
    if (tid < 16) bias1[tid] = b1[(tid >> 2) * 512 + cell0 + (tid & 3)];
    for (int i = tid; i < 512; i += 256) {
        c0s[i] = 0.f; c1s[i] = 0.f;
        g_h0[0][cell0 * 128 + i] = 0.f;
        g_h1[0][cell0 * 128 + i] = 0.f;
    }
    grid_sync();

    const int kg  = tid >> 7;
    const int t7  = tid & 127;
    const int rg4 = (t7 >> 2) << 2;     // rows rg4..rg4+3
    const int ct4 = (t7 & 3) << 2;      // local cols ct4..ct4+3
    float* tb = tiles + kg * 8448;

    // epilogue mapping: update u=0 -> (row0, cl0), u=1 -> (row0, cl0+2)
    const int row0 = tid & 127;
    const int cl0  = tid >> 7;
    const int cl1  = cl0 + 2;

    for (int t = 0; t < Tt; t++) {
        const int p = t & 1;

        // prefetch G0in for epilogue (hidden under GEMM)
        float g0a[4], g0b[4];
        {
            size_t base = (size_t)t * FH * Bb;
#pragma unroll
            for (int g = 0; g < 4; g++) {
                g0a[g] = g_G0in[base + (size_t)(g * 512 + cell0 + cl0) * Bb + row0];
                g0b[g] = g_G0in[base + (size_t)(g * 512 + cell0 + cl1) * Bb + row0];
            }
        }

        // ---- phase 1: layer-0 recurrent GEMM + cell update ----
        unsigned long long acc[8];
#pragma unroll
        for (int i = 0; i < 8; i++) acc[i] = 0ULL;
        gemm_part((const float4*)(g_h0[p] + kg * 256 * 128), w0s + kg * 4096, tb, 8,
                  t7, rg4, ct4, acc);
#pragma unroll
        for (int c = 0; c < 4; c++) {
            float4 v;
            unpack2(acc[c * 2],     v.x, v.y);
            unpack2(acc[c * 2 + 1], v.z, v.w);
            *(float4*)&gsum[(kg * 16 + ct4 + c) * 132 + rg4] = v;
        }
        __syncthreads();
        {
            float* hdst = g_h0[1 - p];
            float gi = gsum[(0  + cl0) * 132 + row0] + gsum[(16 + cl0) * 132 + row0] + g0a[0];
            float gj = gsum[(4  + cl0) * 132 + row0] + gsum[(20 + cl0) * 132 + row0] + g0a[1];
            float gf = gsum[(8  + cl0) * 132 + row0] + gsum[(24 + cl0) * 132 + row0] + g0a[2];
            float go = gsum[(12 + cl0) * 132 + row0] + gsum[(28 + cl0) * 132 + row0] + g0a[3];
            float c  = c0s[cl0 * 128 + row0];
            float cn = c * sigm(gf + 1.0f) + sigm(gi) * tanh_(gj);
            c0s[cl0 * 128 + row0] = cn;
            hdst[(cell0 + cl0) * 128 + row0] = tanh_(cn) * sigm(go);

            gi = gsum[(0  + cl1) * 132 + row0] + gsum[(16 + cl1) * 132 + row0] + g0b[0];
            gj = gsum[(4  + cl1) * 132 + row0] + gsum[(20 + cl1) * 132 + row0] + g0b[1];
            gf = gsum[(8  + cl1) * 132 + row0] + gsum[(24 + cl1) * 132 + row0] + g0b[2];
            go = gsum[(12 + cl1) * 132 + row0] + gsum[(28 + cl1) * 132 + row0] + g0b[3];
            c  = c1s[0]; // placeholder to keep symmetry? no:
            c  = c0s[cl1 * 128 + row0];
            cn = c * sigm(gf + 1.0f) + sigm(gi) * tanh_(gj);
            c0s[cl1 * 128 + row0] = cn;
            hdst[(cell0 + cl1) * 128 + row0] = tanh_(cn) * sigm(go);
        }
        grid_sync();

        // ---- phase 2: layer-1 GEMM over [h0_cur ; h1_prev] + cell update ----
#pragma unroll
        for (int i = 0; i < 8; i++) acc[i] = 0ULL;
        const float* hsrc2 = (kg == 0) ? g_h0[1 - p] : g_h1[p];
        gemm_part((const float4*)hsrc2, w1s + kg * 8192, tb, 16, t7, rg4, ct4, acc);
#pragma unroll
        for (int c = 0; c < 4; c++) {
            float4 v;
            unpack2(acc[c * 2],     v.x, v.y);
            unpack2(acc[c * 2 + 1], v.z, v.w);
            *(float4*)&gsum[(kg * 16 + ct4 + c) * 132 + rg4] = v;
        }
        __syncthreads();
        {
            float* hdst = g_h1[1 - p];
            float gi = gsum[(0  + cl0) * 132 + row0] + gsum[(16 + cl0) * 132 + row0] + bias1[0  + cl0];
            float gj = gsum[(4  + cl0) * 132 + row0] + gsum[(20 + cl0) * 132 + row0] + bias1[4  + cl0];
            float gf = gsum[(8  + cl0) * 132 + row0] + gsum[(24 + cl0) * 132 + row0] + bias1[8  + cl0];
            float go = gsum[(12 + cl0) * 132 + row0] + gsum[(28 + cl0) * 132 + row0] + bias1[12 + cl0];
            float c  = c1s[cl0 * 128 + row0];
            float cn = c * sigm(gf + 1.0f) + sigm(gi) * tanh_(gj);
            c1s[cl0 * 128 + row0] = cn;
            hdst[(cell0 + cl0) * 128 + row0] = tanh_(cn) * sigm(go);

            gi = gsum[(0  + cl1) * 132 + row0] + gsum[(16 + cl1) * 132 + row0] + bias1[0  + cl1];
            gj = gsum[(4  + cl1) * 132 + row0] + gsum[(20 + cl1) * 132 + row0] + bias1[4  + cl1];
            gf = gsum[(8  + cl1) * 132 + row0] + gsum[(24 + cl1) * 132 + row0] + bias1[8  + cl1];
            go = gsum[(12 + cl1) * 132 + row0] + gsum[(28 + cl1) * 132 + row0] + bias1[12 + cl1];
            c  = c1s[cl1 * 128 + row0];
            cn = c * sigm(gf + 1.0f) + sigm(gi) * tanh_(gj);
            c1s[cl1 * 128 + row0] = cn;
            hdst[(cell0 + cl1) * 128 + row0] = tanh_(cn) * sigm(go);
        }
        grid_sync();
    }

    // ---- final logits: CTA b computes out[b][0..1]; final h1 is buffer 0 ----
    {
        int b = cta;
        float s0 = 0.f, s1 = 0.f;
        for (int n = tid; n < Hh; n += 256) {
            float h = __ldcg(&g_h1[0][n * 128 + b]);
            s0 += h * Wd[n * 2];
            s1 += h * Wd[n * 2 + 1];
        }
        gsum[tid] = s0;
        gsum[256 + tid] = s1;
        __syncthreads();
        for (int s = 128; s > 0; s >>= 1) {
            if (tid < s) {
                gsum[tid] += gsum[tid + s];
                gsum[256 + tid] += gsum[256 + tid + s];
            }
            __syncthreads();
        }
        if (tid == 0) {
            out[b * 2]     = gsum[0]   + bd[0];
            out[b * 2 + 1] = gsum[256] + bd[1];
        }
    }
}

// ---------------- launch ----------------
extern "C" void kernel_launch(void* const* d_in, const int* in_sizes, int n_in,
                              void* d_out, int out_size)
{
    const void*  x   = d_in[0];
    const float* emb = (const float*)d_in[1];
    const float* W0  = (const float*)d_in[2];
    const float* b0  = (const float*)d_in[3];
    const float* W1  = (const float*)d_in[4];
    const float* b1  = (const float*)d_in[5];
    const float* Wd  = (const float*)d_in[6];
    const float* bd  = (const float*)d_in[7];
    float* out = (float*)d_out;
    (void)in_sizes; (void)n_in; (void)out_size;

    static int smem_set = 0;
    if (!smem_set) {
        cudaFuncSetAttribute(lstm_persist, cudaFuncAttributeMaxDynamicSharedMemorySize,
                             SMEM_FLOATS * sizeof(float));
        smem_set = 1;
    }

    detect_kernel<<<1, 1>>>(x);
    reset_kernel<<<1, 1>>>();

    dim3 gp(FH / 64, (Bb * Tt) / 64);        // (32, 512)
    gemm_in_kernel<<<gp, 256>>>(x, emb, W0, b0);

    lstm_persist<<<NCTA, 256, SMEM_FLOATS * sizeof(float)>>>(W0, W1, b1, Wd, bd, out);
}

// round 7
// speedup vs baseline: 2.1454x; 1.2704x over previous
#include <cuda_runtime.h>
#include <cuda_bf16.h>

#define Bb 128
#define Tt 256
#define Hh 512
#define Ee 300
#define Vv 50000
#define FH 2048
#define NCTA 128

#define SMEM_BYTES 115264
// smem offsets (bytes)
#define W0F_OFF 0
#define W1F_OFF 32768
#define DSM0_OFF 98304
#define DSM1_OFF 106752
#define BIAS_OFF 115200

// ---------------- globals ----------------
__device__ float g_G0in[(size_t)Tt * FH * Bb];   // [t][gatecol][b]
// h planes in A-fragment layout: u32 (kp,row); uint4 idx = kt*256 + wm*32 + lane
//   .x=(row, kp) .y=(row+8, kp) .z=(row, kp+4) .w=(row+8, kp+4);  row=wm*16+(lane>>2), kp=kt*8+(lane&3)
__device__ __align__(16) unsigned char g_h0hi[2][131072];
__device__ __align__(16) unsigned char g_h0lo[2][131072];
__device__ __align__(16) unsigned char g_h1hi[2][131072];
__device__ __align__(16) unsigned char g_h1lo[2][131072];
__device__ float g_h1f[Hh * Bb];
__device__ int g_x64;
__device__ unsigned g_bar_arrive;
__device__ volatile unsigned g_bar_gen;

// ---------------- helpers ----------------
__device__ __forceinline__ unsigned long long pack2(float lo, float hi) {
    unsigned long long r; asm("mov.b64 %0, {%1, %2};" : "=l"(r) : "f"(lo), "f"(hi)); return r;
}
__device__ __forceinline__ void unpack2(unsigned long long v, float& lo, float& hi) {
    asm("mov.b64 {%0, %1}, %2;" : "=f"(lo), "=f"(hi) : "l"(v));
}
__device__ __forceinline__ unsigned long long fma2(unsigned long long a, unsigned long long b, unsigned long long c) {
    unsigned long long d; asm("fma.rn.f32x2 %0, %1, %2, %3;" : "=l"(d) : "l"(a), "l"(b), "l"(c)); return d;
}
__device__ __forceinline__ float ex2f(float x) { float y; asm("ex2.approx.f32 %0, %1;" : "=f"(y) : "f"(x)); return y; }
__device__ __forceinline__ float rcpf(float x) { float y; asm("rcp.approx.f32 %0, %1;" : "=f"(y) : "f"(x)); return y; }
__device__ __forceinline__ float sigm(float x) { return rcpf(1.0f + ex2f(-1.4426950408889634f * x)); }
__device__ __forceinline__ float tanh_(float x) { return fmaf(2.0f, sigm(2.0f * x), -1.0f); }
__device__ __forceinline__ unsigned short bfr(float f) {
    unsigned short u; asm("cvt.rn.bf16.f32 %0, %1;" : "=h"(u) : "f"(f)); return u;
}
__device__ __forceinline__ float bf2f(unsigned short u) {
    return __uint_as_float((unsigned)u << 16);
}
// low 16 bits = even element (smaller k), high = odd
__device__ __forceinline__ unsigned pkb(float even, float odd) {
    return (unsigned)bfr(even) | ((unsigned)bfr(odd) << 16);
}

__device__ __forceinline__ void mma_bf16(float d[4], const uint4& a, unsigned b0, unsigned b1) {
    asm volatile("mma.sync.aligned.m16n8k16.row.col.f32.bf16.bf16.f32 "
        "{%0,%1,%2,%3}, {%4,%5,%6,%7}, {%8,%9}, {%0,%1,%2,%3};"
        : "+f"(d[0]), "+f"(d[1]), "+f"(d[2]), "+f"(d[3])
        : "r"(a.x), "r"(a.y), "r"(a.z), "r"(a.w), "r"(b0), "r"(b1));
}

__device__ __forceinline__ void grid_sync() {
    __syncthreads();
    if (threadIdx.x == 0) {
        unsigned gen = g_bar_gen;
        __threadfence();
        if (atomicAdd(&g_bar_arrive, 1u) == NCTA - 1) {
            g_bar_arrive = 0; __threadfence(); g_bar_gen = gen + 1;
        } else {
            while (g_bar_gen == gen) { }
        }
        __threadfence();
    }
    __syncthreads();
}

// ---------------- detect / reset ----------------
__global__ void detect_kernel(const void* x) {
    const long long* p = (const long long*)x;
    int ok64 = 1;
    for (int i = 0; i < 16; i++) { long long v = p[i]; if (v < 0 || v >= Vv) ok64 = 0; }
    g_x64 = ok64;
}
__device__ __forceinline__ int token_at(const void* x, int idx) {
    if (g_x64) return (int)((const long long*)x)[idx];
    return ((const int*)x)[idx];
}
__global__ void reset_kernel() { g_bar_arrive = 0; g_bar_gen = 0; }

// ---------------- G0in precompute (validated R2) ----------------
__global__ void __launch_bounds__(256) gemm_in_kernel(
    const void* __restrict__ x, const float* __restrict__ emb,
    const float* __restrict__ W0, const float* __restrict__ b0)
{
    __shared__ __align__(16) float As[20][66];
    __shared__ __align__(16) float Bs[20][64];
    __shared__ float Gs[64][65];
    __shared__ int rows[64];

    int tid = threadIdx.x;
    int n0 = blockIdx.x * 64;
    int m0 = blockIdx.y * 64;

    if (tid < 64) {
        int m = m0 + tid;
        rows[tid] = token_at(x, (m & 127) * Tt + (m >> 7));
    }
    __syncthreads();

    int ty = tid >> 4, tx = tid & 15;
    unsigned long long acc[2][4];
#pragma unroll
    for (int i = 0; i < 2; i++)
#pragma unroll
        for (int j = 0; j < 4; j++) acc[i][j] = 0ULL;

    for (int k0 = 0; k0 < Ee; k0 += 20) {
#pragma unroll
        for (int i = 0; i < 5; i++) {
            int idx = i * 256 + tid;
            As[idx >> 6][idx & 63] = emb[rows[idx & 63] * Ee + k0 + (idx >> 6)];
        }
#pragma unroll
        for (int i = 0; i < 5; i++) {
            int idx = i * 256 + tid;
            Bs[idx >> 6][idx & 63] = W0[(k0 + (idx >> 6)) * FH + n0 + (idx & 63)];
        }
        __syncthreads();
#pragma unroll
        for (int kk = 0; kk < 20; kk++) {
            float2 a01 = *(const float2*)&As[kk][ty * 4];
            float2 a23 = *(const float2*)&As[kk][ty * 4 + 2];
            float4 b4  = *(const float4*)&Bs[kk][tx * 4];
            unsigned long long ap0 = pack2(a01.x, a01.y);
            unsigned long long ap1 = pack2(a23.x, a23.y);
            unsigned long long bp;
            bp = pack2(b4.x, b4.x); acc[0][0] = fma2(ap0, bp, acc[0][0]); acc[1][0] = fma2(ap1, bp, acc[1][0]);
            bp = pack2(b4.y, b4.y); acc[0][1] = fma2(ap0, bp, acc[0][1]); acc[1][1] = fma2(ap1, bp, acc[1][1]);
            bp = pack2(b4.z, b4.z); acc[0][2] = fma2(ap0, bp, acc[0][2]); acc[1][2] = fma2(ap1, bp, acc[1][2]);
            bp = pack2(b4.w, b4.w); acc[0][3] = fma2(ap0, bp, acc[0][3]); acc[1][3] = fma2(ap1, bp, acc[1][3]);
        }
        __syncthreads();
    }

#pragma unroll
    for (int j = 0; j < 4; j++) {
        int c = tx * 4 + j;
        float bias = b0[n0 + c];
        float v0, v1, v2, v3;
        unpack2(acc[0][j], v0, v1);
        unpack2(acc[1][j], v2, v3);
        Gs[c][ty * 4 + 0] = v0 + bias;
        Gs[c][ty * 4 + 1] = v1 + bias;
        Gs[c][ty * 4 + 2] = v2 + bias;
        Gs[c][ty * 4 + 3] = v3 + bias;
    }
    __syncthreads();

    int tblk = m0 >> 7, bbase = m0 & 127;
#pragma unroll
    for (int i = 0; i < 16; i++) {
        int e = i * 256 + tid;
        g_G0in[((size_t)tblk * FH + n0 + (e >> 6)) * Bb + bbase + (e & 63)] = Gs[e >> 6][e & 63];
    }
}

// ---------------- persistent warp-MMA LSTM ----------------
// CTA owns 4 cells; 16 cols, col = g*4 + cl (g=gate 0..3 in i,j,f,o order).
__global__ void __launch_bounds__(256, 1) lstm_mma(
    const float* __restrict__ W0, const float* __restrict__ W1,
    const float* __restrict__ b1, const float* __restrict__ Wd,
    const float* __restrict__ bd, float* __restrict__ out)
{
    extern __shared__ char smc[];
    uint4* w0f = (uint4*)(smc + W0F_OFF);   // [kt32][nt2][lane32] {whi0,whi1,wlo0,wlo1}
    uint4* w1f = (uint4*)(smc + W1F_OFF);   // [kt64][nt2][lane32]
    float* dsm0 = (float*)(smc + DSM0_OFF); // [col16][row128] stride 132
    float* dsm1 = (float*)(smc + DSM1_OFF);
    float* bias1s = (float*)(smc + BIAS_OFF);

    const int tid = threadIdx.x;
    const int cta = blockIdx.x;
    const int cell0 = cta * 4;
    const int wm = tid >> 5;
    const int lane = tid & 31;

    // ---- build W fragments (once) ----
    for (int idx = tid; idx < 2048; idx += 256) {
        int kt = idx >> 6, nt = (idx >> 5) & 1, ln = idx & 31;
        int col = nt * 8 + (ln >> 2);
        int gcol = (col >> 2) * 512 + cell0 + (col & 3);
        int kb = kt * 16 + (ln & 3) * 2;
        float v0 = W0[(size_t)(Ee + kb) * FH + gcol];
        float v1 = W0[(size_t)(Ee + kb + 1) * FH + gcol];
        float v8 = W0[(size_t)(Ee + kb + 8) * FH + gcol];
        float v9 = W0[(size_t)(Ee + kb + 9) * FH + gcol];
        unsigned short h0 = bfr(v0), h1 = bfr(v1), h8 = bfr(v8), h9 = bfr(v9);
        w0f[idx] = make_uint4(
            (unsigned)h0 | ((unsigned)h1 << 16),
            (unsigned)h8 | ((unsigned)h9 << 16),
            pkb(v0 - bf2f(h0), v1 - bf2f(h1)),
            pkb(v8 - bf2f(h8), v9 - bf2f(h9)));
    }
    for (int idx = tid; idx < 4096; idx += 256) {
        int kt = idx >> 6, nt = (idx >> 5) & 1, ln = idx & 31;
        int col = nt * 8 + (ln >> 2);
        int gcol = (col >> 2) * 512 + cell0 + (col & 3);
        int kb = kt * 16 + (ln & 3) * 2;
        float v0 = W1[(size_t)kb * FH + gcol];
        float v1 = W1[(size_t)(kb + 1) * FH + gcol];
        float v8 = W1[(size_t)(kb + 8) * FH + gcol];
        float v9 = W1[(size_t)(kb + 9) * FH + gcol];
        unsigned short h0 = bfr(v0), h1 = bfr(v1), h8 = bfr(v8), h9 = bfr(v9);
        w1f[idx] = make_uint4(
            (unsigned)h0 | ((unsigned)h1 << 16),
            (unsigned)h8 | ((unsigned)h9 << 16),
            pkb(v0 - bf2f(h0), v1 - bf2f(h1)),
            pkb(v8 - bf2f(h8), v9 - bf2f(h9)));
    }
    if (tid < 16) bias1s[tid] = b1[(tid >> 2) * 512 + cell0 + (tid & 3)];

    // zero initial h buffers [1]
    if (tid < 64) {
        uint4 z = make_uint4(0, 0, 0, 0);
        size_t o = (size_t)cta * 64 + tid;
        ((uint4*)g_h0hi[1])[o] = z; ((uint4*)g_h0lo[1])[o] = z;
        ((uint4*)g_h1hi[1])[o] = z; ((uint4*)g_h1lo[1])[o] = z;
    }
    grid_sync();

    // ---- epilogue thread mapping: (row, cells cell0+2u, cell0+2u+1) ----
    const int row = tid & 127;
    const int u = tid >> 7;
    const int cl_e = 2 * u, cl_o = 2 * u + 1;
    const int kp_g = cta * 2 + u;
    const int kt_e = kp_g >> 3, kpi = kp_g & 7;
    const int rr = row & 15;
    const unsigned eoff = (unsigned)(kt_e * 4096 + (row >> 4) * 512 +
                          (((rr & 7) << 2) | (kpi & 3)) * 16 +
                          ((kpi >= 4 ? 2 : 0) + (rr >= 8 ? 1 : 0)) * 4);
    float c0a = 0.f, c0b = 0.f, c1a = 0.f, c1b = 0.f;

    const unsigned fbase = wm * 32 + lane;

    for (int i = 0; i <= Tt; i++) {
        const int pA = (i + 1) & 1;   // read h0(i-1); write h1(i-1)
        const int pW = i & 1;         // write h0(i); read h1(i-2)
        const bool doL0 = (i < Tt);
        const bool doL1 = (i > 0);

        float g0v[8];
        if (doL0) {
#pragma unroll
            for (int g = 0; g < 4; g++) {
                g0v[g]     = __ldcg(&g_G0in[((size_t)i * FH + g * 512 + cell0 + cl_e) * Bb + row]);
                g0v[4 + g] = __ldcg(&g_G0in[((size_t)i * FH + g * 512 + cell0 + cl_o) * Bb + row]);
            }
        }

        float d0[2][4], d1[2][4];
#pragma unroll
        for (int n = 0; n < 2; n++)
#pragma unroll
            for (int q = 0; q < 4; q++) { d0[n][q] = 0.f; d1[n][q] = 0.f; }

        // ---- K pass 1: A = h0(i-1), feeds W0 (L0) and W1 rows 0..511 (L1) ----
        {
            const uint4* ah = (const uint4*)g_h0hi[pA] + fbase;
            const uint4* al = (const uint4*)g_h0lo[pA] + fbase;
            for (int kt = 0; kt < 32; kt++) {
                uint4 A = __ldcg(ah + kt * 256);
                uint4 L = __ldcg(al + kt * 256);
#pragma unroll
                for (int nt = 0; nt < 2; nt++) {
                    if (doL0) {
                        uint4 w = w0f[(kt * 2 + nt) * 32 + lane];
                        mma_bf16(d0[nt], A, w.x, w.y);
                        mma_bf16(d0[nt], L, w.x, w.y);
                        mma_bf16(d0[nt], A, w.z, w.w);
                    }
                    if (doL1) {
                        uint4 w = w1f[(kt * 2 + nt) * 32 + lane];
                        mma_bf16(d1[nt], A, w.x, w.y);
                        mma_bf16(d1[nt], L, w.x, w.y);
                        mma_bf16(d1[nt], A, w.z, w.w);
                    }
                }
            }
        }
        // ---- K pass 2: A = h1(i-2), W1 rows 512..1023 ----
        if (doL1) {
            const uint4* ah = (const uint4*)g_h1hi[pW] + fbase;
            const uint4* al = (const uint4*)g_h1lo[pW] + fbase;
            for (int kt = 0; kt < 32; kt++) {
                uint4 A = __ldcg(ah + kt * 256);
                uint4 L = __ldcg(al + kt * 256);
#pragma unroll
                for (int nt = 0; nt < 2; nt++) {
                    uint4 w = w1f[((32 + kt) * 2 + nt) * 32 + lane];
                    mma_bf16(d1[nt], A, w.x, w.y);
                    mma_bf16(d1[nt], L, w.x, w.y);
                    mma_bf16(d1[nt], A, w.z, w.w);
                }
            }
        }

        // ---- D -> SMEM transpose ----
        {
            int r0 = wm * 16 + (lane >> 2);
#pragma unroll
            for (int nt = 0; nt < 2; nt++) {
                int c = nt * 8 + (lane & 3) * 2;
                if (doL0) {
                    dsm0[c * 132 + r0]           = d0[nt][0];
                    dsm0[(c + 1) * 132 + r0]     = d0[nt][1];
                    dsm0[c * 132 + r0 + 8]       = d0[nt][2];
                    dsm0[(c + 1) * 132 + r0 + 8] = d0[nt][3];
                }
                if (doL1) {
                    dsm1[c * 132 + r0]           = d1[nt][0];
                    dsm1[(c + 1) * 132 + r0]     = d1[nt][1];
                    dsm1[c * 132 + r0 + 8]       = d1[nt][2];
                    dsm1[(c + 1) * 132 + r0 + 8] = d1[nt][3];
                }
            }
        }
        __syncthreads();

        // ---- L0 epilogue: write h0(i) ----
        if (doL0) {
            float gi = dsm0[(0 + cl_e) * 132 + row] + g0v[0];
            float gj = dsm0[(4 + cl_e) * 132 + row] + g0v[1];
            float gf = dsm0[(8 + cl_e) * 132 + row] + g0v[2];
            float go = dsm0[(12 + cl_e) * 132 + row] + g0v[3];
            float cn = c0a * sigm(gf + 1.0f) + sigm(gi) * tanh_(gj);
            c0a = cn;
            float he = tanh_(cn) * sigm(go);

            gi = dsm0[(0 + cl_o) * 132 + row] + g0v[4];
            gj = dsm0[(4 + cl_o) * 132 + row] + g0v[5];
            gf = dsm0[(8 + cl_o) * 132 + row] + g0v[6];
            go = dsm0[(12 + cl_o) * 132 + row] + g0v[7];
            cn = c0b * sigm(gf + 1.0f) + sigm(gi) * tanh_(gj);
            c0b = cn;
            float ho = tanh_(cn) * sigm(go);

            unsigned short e16 = bfr(he), o16 = bfr(ho);
            *(unsigned*)(g_h0hi[pW] + eoff) = (unsigned)e16 | ((unsigned)o16 << 16);
            *(unsigned*)(g_h0lo[pW] + eoff) = pkb(he - bf2f(e16), ho - bf2f(o16));
        }
        // ---- L1 epilogue: write h1(i-1) ----
        if (doL1) {
            float gi = dsm1[(0 + cl_e) * 132 + row] + bias1s[0 + cl_e];
            float gj = dsm1[(4 + cl_e) * 132 + row] + bias1s[4 + cl_e];
            float gf = dsm1[(8 + cl_e) * 132 + row] + bias1s[8 + cl_e];
            float go = dsm1[(12 + cl_e) * 132 + row] + bias1s[12 + cl_e];
            float cn = c1a * sigm(gf + 1.0f) + sigm(gi) * tanh_(gj);
            c1a = cn;
            float he = tanh_(cn) * sigm(go);

            gi = dsm1[(0 + cl_o) * 132 + row] + bias1s[0 + cl_o];
            gj = dsm1[(4 + cl_o) * 132 + row] + bias1s[4 + cl_o];
            gf = dsm1[(8 + cl_o) * 132 + row] + bias1s[8 + cl_o];
            go = dsm1[(12 + cl_o) * 132 + row] + bias1s[12 + cl_o];
            cn = c1b * sigm(gf + 1.0f) + sigm(gi) * tanh_(gj);
            c1b = cn;
            float ho = tanh_(cn) * sigm(go);

            unsigned short e16 = bfr(he), o16 = bfr(ho);
            *(unsigned*)(g_h1hi[pA] + eoff) = (unsigned)e16 | ((unsigned)o16 << 16);
            *(unsigned*)(g_h1lo[pA] + eoff) = pkb(he - bf2f(e16), ho - bf2f(o16));
            if (i == Tt) {
                g_h1f[(cell0 + cl_e) * Bb + row] = he;
                g_h1f[(cell0 + cl_o) * Bb + row] = ho;
            }
        }
        grid_sync();
    }

    // ---- final logits: CTA = batch row ----
    {
        float s0 = 0.f, s1 = 0.f;
        for (int n = tid; n < Hh; n += 256) {
            float h = __ldcg(&g_h1f[n * Bb + cta]);
            s0 += h * Wd[n * 2];
            s1 += h * Wd[n * 2 + 1];
        }
        float* red = dsm0;
        red[tid] = s0; red[256 + tid] = s1;
        __syncthreads();
        for (int st = 128; st > 0; st >>= 1) {
            if (tid < st) {
                red[tid] += red[tid + st];
                red[256 + tid] += red[256 + tid + st];
            }
            __syncthreads();
        }
        if (tid == 0) {
            out[cta * 2]     = red[0]   + bd[0];
            out[cta * 2 + 1] = red[256] + bd[1];
        }
    }
}

// ---------------- launch ----------------
extern "C" void kernel_launch(void* const* d_in, const int* in_sizes, int n_in,
                              void* d_out, int out_size)
{
    const void*  x   = d_in[0];
    const float* emb = (const float*)d_in[1];
    const float* W0  = (const float*)d_in[2];
    const float* b0  = (const float*)d_in[3];
    const float* W1  = (const float*)d_in[4];
    const float* b1  = (const float*)d_in[5];
    const float* Wd  = (const float*)d_in[6];
    const float* bd  = (const float*)d_in[7];
    float* out = (float*)d_out;
    (void)in_sizes; (void)n_in; (void)out_size;

    static int init_done = 0;
    if (!init_done) {
        cudaFuncSetAttribute(lstm_mma, cudaFuncAttributeMaxDynamicSharedMemorySize, SMEM_BYTES);
        init_done = 1;
    }

    detect_kernel<<<1, 1>>>(x);
    reset_kernel<<<1, 1>>>();

    dim3 gp(FH / 64, (Bb * Tt) / 64);
    gemm_in_kernel<<<gp, 256>>>(x, emb, W0, b0);

    lstm_mma<<<NCTA, 256, SMEM_BYTES>>>(W0, W1, b1, Wd, bd, out);
}

// round 8
// speedup vs baseline: 2.3740x; 1.1066x over previous
#include <cuda_runtime.h>
#include <cuda_bf16.h>

#define Bb 128
#define Tt 256
#define Hh 512
#define Ee 300
#define Vv 50000
#define FH 2048
#define NCTA 128

#define SMEM_BYTES 115264
#define W0F_OFF 0
#define W1F_OFF 32768
#define DSM0_OFF 98304
#define DSM1_OFF 106752
#define BIAS_OFF 115200

// ---------------- globals ----------------
__device__ float g_G0in[(size_t)Tt * FH * Bb];   // [t][gatecol][b]
// h planes in A-fragment layout (validated R6):
//   uint4 idx = kt*256 + wm*32 + lane; row=wm*16+(lane>>2), kp=kt*8+(lane&3)
//   .x=(row,kp) .y=(row+8,kp) .z=(row,kp+4) .w=(row+8,kp+4); u32 = bf16 pair (2kp, 2kp+1)
__device__ __align__(16) unsigned char g_h0hi[2][131072];
__device__ __align__(16) unsigned char g_h0lo[2][131072];
__device__ __align__(16) unsigned char g_h1hi[2][131072];
__device__ __align__(16) unsigned char g_h1lo[2][131072];
__device__ float g_h1f[Hh * Bb];
__device__ int g_x64;
__device__ unsigned g_bar_arrive;
__device__ volatile unsigned g_bar_gen;

// ---------------- helpers ----------------
__device__ __forceinline__ unsigned long long pack2(float lo, float hi) {
    unsigned long long r; asm("mov.b64 %0, {%1, %2};" : "=l"(r) : "f"(lo), "f"(hi)); return r;
}
__device__ __forceinline__ void unpack2(unsigned long long v, float& lo, float& hi) {
    asm("mov.b64 {%0, %1}, %2;" : "=f"(lo), "=f"(hi) : "l"(v));
}
__device__ __forceinline__ unsigned long long fma2(unsigned long long a, unsigned long long b, unsigned long long c) {
    unsigned long long d; asm("fma.rn.f32x2 %0, %1, %2, %3;" : "=l"(d) : "l"(a), "l"(b), "l"(c)); return d;
}
__device__ __forceinline__ float ex2f(float x) { float y; asm("ex2.approx.f32 %0, %1;" : "=f"(y) : "f"(x)); return y; }
__device__ __forceinline__ float rcpf(float x) { float y; asm("rcp.approx.f32 %0, %1;" : "=f"(y) : "f"(x)); return y; }
__device__ __forceinline__ float sigm(float x) { return rcpf(1.0f + ex2f(-1.4426950408889634f * x)); }
__device__ __forceinline__ float tanh_(float x) { return fmaf(2.0f, sigm(2.0f * x), -1.0f); }
__device__ __forceinline__ unsigned short bfr(float f) {
    unsigned short u; asm("cvt.rn.bf16.f32 %0, %1;" : "=h"(u) : "f"(f)); return u;
}
__device__ __forceinline__ float bf2f(unsigned short u) {
    return __uint_as_float((unsigned)u << 16);
}
__device__ __forceinline__ unsigned pkb(float even, float odd) {
    return (unsigned)bfr(even) | ((unsigned)bfr(odd) << 16);
}

__device__ __forceinline__ void mma_bf16(float d[4], const uint4& a, unsigned b0, unsigned b1) {
    asm volatile("mma.sync.aligned.m16n8k16.row.col.f32.bf16.bf16.f32 "
        "{%0,%1,%2,%3}, {%4,%5,%6,%7}, {%8,%9}, {%0,%1,%2,%3};"
        : "+f"(d[0]), "+f"(d[1]), "+f"(d[2]), "+f"(d[3])
        : "r"(a.x), "r"(a.y), "r"(a.z), "r"(a.w), "r"(b0), "r"(b1));
}

__device__ __forceinline__ void grid_sync() {
    __syncthreads();
    if (threadIdx.x == 0) {
        unsigned gen = g_bar_gen;
        __threadfence();
        if (atomicAdd(&g_bar_arrive, 1u) == NCTA - 1) {
            g_bar_arrive = 0; __threadfence(); g_bar_gen = gen + 1;
        } else {
            while (g_bar_gen == gen) { }
        }
        __threadfence();
    }
    __syncthreads();
}

// ---------------- detect / reset ----------------
__global__ void detect_kernel(const void* x) {
    const long long* p = (const long long*)x;
    int ok64 = 1;
    for (int i = 0; i < 16; i++) { long long v = p[i]; if (v < 0 || v >= Vv) ok64 = 0; }
    g_x64 = ok64;
}
__device__ __forceinline__ int token_at(const void* x, int idx) {
    if (g_x64) return (int)((const long long*)x)[idx];
    return ((const int*)x)[idx];
}
__global__ void reset_kernel() { g_bar_arrive = 0; g_bar_gen = 0; }

// ---------------- G0in precompute (validated R2) ----------------
__global__ void __launch_bounds__(256) gemm_in_kernel(
    const void* __restrict__ x, const float* __restrict__ emb,
    const float* __restrict__ W0, const float* __restrict__ b0)
{
    __shared__ __align__(16) float As[20][66];
    __shared__ __align__(16) float Bs[20][64];
    __shared__ float Gs[64][65];
    __shared__ int rows[64];

    int tid = threadIdx.x;
    int n0 = blockIdx.x * 64;
    int m0 = blockIdx.y * 64;

    if (tid < 64) {
        int m = m0 + tid;
        rows[tid] = token_at(x, (m & 127) * Tt + (m >> 7));
    }
    __syncthreads();

    int ty = tid >> 4, tx = tid & 15;
    unsigned long long acc[2][4];
#pragma unroll
    for (int i = 0; i < 2; i++)
#pragma unroll
        for (int j = 0; j < 4; j++) acc[i][j] = 0ULL;

    for (int k0 = 0; k0 < Ee; k0 += 20) {
#pragma unroll
        for (int i = 0; i < 5; i++) {
            int idx = i * 256 + tid;
            As[idx >> 6][idx & 63] = emb[rows[idx & 63] * Ee + k0 + (idx >> 6)];
        }
#pragma unroll
        for (int i = 0; i < 5; i++) {
            int idx = i * 256 + tid;
            Bs[idx >> 6][idx & 63] = W0[(k0 + (idx >> 6)) * FH + n0 + (idx & 63)];
        }
        __syncthreads();
#pragma unroll
        for (int kk = 0; kk < 20; kk++) {
            float2 a01 = *(const float2*)&As[kk][ty * 4];
            float2 a23 = *(const float2*)&As[kk][ty * 4 + 2];
            float4 b4  = *(const float4*)&Bs[kk][tx * 4];
            unsigned long long ap0 = pack2(a01.x, a01.y);
            unsigned long long ap1 = pack2(a23.x, a23.y);
            unsigned long long bp;
            bp = pack2(b4.x, b4.x); acc[0][0] = fma2(ap0, bp, acc[0][0]); acc[1][0] = fma2(ap1, bp, acc[1][0]);
            bp = pack2(b4.y, b4.y); acc[0][1] = fma2(ap0, bp, acc[0][1]); acc[1][1] = fma2(ap1, bp, acc[1][1]);
            bp = pack2(b4.z, b4.z); acc[0][2] = fma2(ap0, bp, acc[0][2]); acc[1][2] = fma2(ap1, bp, acc[1][2]);
            bp = pack2(b4.w, b4.w); acc[0][3] = fma2(ap0, bp, acc[0][3]); acc[1][3] = fma2(ap1, bp, acc[1][3]);
        }
        __syncthreads();
    }

#pragma unroll
    for (int j = 0; j < 4; j++) {
        int c = tx * 4 + j;
        float bias = b0[n0 + c];
        float v0, v1, v2, v3;
        unpack2(acc[0][j], v0, v1);
        unpack2(acc[1][j], v2, v3);
        Gs[c][ty * 4 + 0] = v0 + bias;
        Gs[c][ty * 4 + 1] = v1 + bias;
        Gs[c][ty * 4 + 2] = v2 + bias;
        Gs[c][ty * 4 + 3] = v3 + bias;
    }
    __syncthreads();

    int tblk = m0 >> 7, bbase = m0 & 127;
#pragma unroll
    for (int i = 0; i < 16; i++) {
        int e = i * 256 + tid;
        g_G0in[((size_t)tblk * FH + n0 + (e >> 6)) * Bb + bbase + (e & 63)] = Gs[e >> 6][e & 63];
    }
}

// ---------------- persistent warp-MMA LSTM (16 warps, K-split) ----------------
__global__ void __launch_bounds__(512, 1) lstm_mma(
    const float* __restrict__ W0, const float* __restrict__ W1,
    const float* __restrict__ b1, const float* __restrict__ Wd,
    const float* __restrict__ bd, float* __restrict__ out)
{
    extern __shared__ char smc[];
    uint4* w0f = (uint4*)(smc + W0F_OFF);   // [kt32][nt2][lane32] {whi0,whi1,wlo0,wlo1}
    uint4* w1f = (uint4*)(smc + W1F_OFF);   // [kt64][nt2][lane32]
    float* dsm0 = (float*)(smc + DSM0_OFF); // [col16][132]
    float* dsm1 = (float*)(smc + DSM1_OFF);
    float* bias1s = (float*)(smc + BIAS_OFF);

    const int tid = threadIdx.x;
    const int cta = blockIdx.x;
    const int cell0 = cta * 4;
    const int wid = tid >> 5;
    const int lane = tid & 31;
    const int kh = wid >> 3;        // K-half
    const int wm = wid & 7;         // row group

    // ---- build W fragments (once) ----
    for (int idx = tid; idx < 2048; idx += 512) {
        int kt = idx >> 6, nt = (idx >> 5) & 1, ln = idx & 31;
        int col = nt * 8 + (ln >> 2);
        int gcol = (col >> 2) * 512 + cell0 + (col & 3);
        int kb = kt * 16 + (ln & 3) * 2;
        float v0 = W0[(size_t)(Ee + kb) * FH + gcol];
        float v1 = W0[(size_t)(Ee + kb + 1) * FH + gcol];
        float v8 = W0[(size_t)(Ee + kb + 8) * FH + gcol];
        float v9 = W0[(size_t)(Ee + kb + 9) * FH + gcol];
        unsigned short h0 = bfr(v0), h1 = bfr(v1), h8 = bfr(v8), h9 = bfr(v9);
        w0f[idx] = make_uint4(
            (unsigned)h0 | ((unsigned)h1 << 16),
            (unsigned)h8 | ((unsigned)h9 << 16),
            pkb(v0 - bf2f(h0), v1 - bf2f(h1)),
            pkb(v8 - bf2f(h8), v9 - bf2f(h9)));
    }
    for (int idx = tid; idx < 4096; idx += 512) {
        int kt = idx >> 6, nt = (idx >> 5) & 1, ln = idx & 31;
        int col = nt * 8 + (ln >> 2);
        int gcol = (col >> 2) * 512 + cell0 + (col & 3);
        int kb = kt * 16 + (ln & 3) * 2;
        float v0 = W1[(size_t)kb * FH + gcol];
        float v1 = W1[(size_t)(kb + 1) * FH + gcol];
        float v8 = W1[(size_t)(kb + 8) * FH + gcol];
        float v9 = W1[(size_t)(kb + 9) * FH + gcol];
        unsigned short h0 = bfr(v0), h1 = bfr(v1), h8 = bfr(v8), h9 = bfr(v9);
        w1f[idx] = make_uint4(
            (unsigned)h0 | ((unsigned)h1 << 16),
            (unsigned)h8 | ((unsigned)h9 << 16),
            pkb(v0 - bf2f(h0), v1 - bf2f(h1)),
            pkb(v8 - bf2f(h8), v9 - bf2f(h9)));
    }
    if (tid < 16) bias1s[tid] = b1[(tid >> 2) * 512 + cell0 + (tid & 3)];

    // zero initial h buffers [1]: 4 planes x 8192 uint4, one per thread chip-wide
    {
        int o = cta * 512 + tid;
        if (o < 8192) {
            uint4 z = make_uint4(0, 0, 0, 0);
            ((uint4*)g_h0hi[1])[o] = z; ((uint4*)g_h0lo[1])[o] = z;
            ((uint4*)g_h1hi[1])[o] = z; ((uint4*)g_h1lo[1])[o] = z;
        }
    }
    grid_sync();

    // epilogue mapping: one cell per thread
    const int row = tid & 127;
    const int u = tid >> 7;               // cell index 0..3
    const int kp_g = (cell0 + u) >> 1;    // u32 pair index in k
    const int half = u & 1;               // which u16 half
    const int kt_e = kp_g >> 3, kpi = kp_g & 7;
    const int rr = row & 15;
    const unsigned eoff = (unsigned)(kt_e * 4096 + (row >> 4) * 512 +
                          (((rr & 7) << 2) | (kpi & 3)) * 16 +
                          ((kpi >= 4 ? 2 : 0) + (rr >= 8 ? 1 : 0)) * 4 + half * 2);
    float c0r = 0.f, c1r = 0.f;

    const unsigned fbase = wm * 32 + lane;
    const unsigned kbase = kh * 16;

    for (int i = 0; i <= Tt; i++) {
        const int pA = (i + 1) & 1;   // read h0(i-1); write h1(i-1)
        const int pW = i & 1;         // write h0(i); read h1(i-2)
        const bool doL0 = (i < Tt);
        const bool doL1 = (i > 0);

        float g0v[4];
        if (doL0) {
#pragma unroll
            for (int g = 0; g < 4; g++)
                g0v[g] = __ldcg(&g_G0in[((size_t)i * FH + g * 512 + cell0 + u) * Bb + row]);
        }

        float d0[2][4], d1[2][4];
#pragma unroll
        for (int n = 0; n < 2; n++)
#pragma unroll
            for (int q = 0; q < 4; q++) { d0[n][q] = 0.f; d1[n][q] = 0.f; }

        // ---- pass 1: A = h0(i-1) K-half; feeds W0 (L0) + W1 rows 0..511 (L1) ----
        {
            const uint4* ah = (const uint4*)g_h0hi[pA];
            const uint4* al = (const uint4*)g_h0lo[pA];
            uint4 A = __ldcg(ah + kbase * 256 + fbase);
            uint4 L = __ldcg(al + kbase * 256 + fbase);
#pragma unroll
            for (int ktl = 0; ktl < 16; ktl++) {
                uint4 An, Ln;
                if (ktl < 15) {
                    An = __ldcg(ah + (kbase + ktl + 1) * 256 + fbase);
                    Ln = __ldcg(al + (kbase + ktl + 1) * 256 + fbase);
                }
                int kt = kbase + ktl;
#pragma unroll
                for (int nt = 0; nt < 2; nt++) {
                    if (doL0) {
                        uint4 w = w0f[(kt * 2 + nt) * 32 + lane];
                        mma_bf16(d0[nt], A, w.x, w.y);
                        mma_bf16(d0[nt], L, w.x, w.y);
                        mma_bf16(d0[nt], A, w.z, w.w);
                    }
                    if (doL1) {
                        uint4 w = w1f[(kt * 2 + nt) * 32 + lane];
                        mma_bf16(d1[nt], A, w.x, w.y);
                        mma_bf16(d1[nt], L, w.x, w.y);
                        mma_bf16(d1[nt], A, w.z, w.w);
                    }
                }
                A = An; L = Ln;
            }
        }
        // ---- pass 2: A = h1(i-2) K-half; W1 rows 512..1023 ----
        if (doL1) {
            const uint4* ah = (const uint4*)g_h1hi[pW];
            const uint4* al = (const uint4*)g_h1lo[pW];
            uint4 A = __ldcg(ah + kbase * 256 + fbase);
            uint4 L = __ldcg(al + kbase * 256 + fbase);
#pragma unroll
            for (int ktl = 0; ktl < 16; ktl++) {
                uint4 An, Ln;
                if (ktl < 15) {
                    An = __ldcg(ah + (kbase + ktl + 1) * 256 + fbase);
                    Ln = __ldcg(al + (kbase + ktl + 1) * 256 + fbase);
                }
                int kt = kbase + ktl;
#pragma unroll
                for (int nt = 0; nt < 2; nt++) {
                    uint4 w = w1f[((32 + kt) * 2 + nt) * 32 + lane];
                    mma_bf16(d1[nt], A, w.x, w.y);
                    mma_bf16(d1[nt], L, w.x, w.y);
                    mma_bf16(d1[nt], A, w.z, w.w);
                }
                A = An; L = Ln;
            }
        }

        // ---- combine K-halves in SMEM: kh=0 stores, kh=1 adds ----
        __syncthreads();
        {
            int r0 = wm * 16 + (lane >> 2);
            if (kh == 0) {
#pragma unroll
                for (int nt = 0; nt < 2; nt++) {
                    int c = nt * 8 + (lane & 3) * 2;
                    dsm0[c * 132 + r0]           = d0[nt][0];
                    dsm0[(c + 1) * 132 + r0]     = d0[nt][1];
                    dsm0[c * 132 + r0 + 8]       = d0[nt][2];
                    dsm0[(c + 1) * 132 + r0 + 8] = d0[nt][3];
                    dsm1[c * 132 + r0]           = d1[nt][0];
                    dsm1[(c + 1) * 132 + r0]     = d1[nt][1];
                    dsm1[c * 132 + r0 + 8]       = d1[nt][2];
                    dsm1[(c + 1) * 132 + r0 + 8] = d1[nt][3];
                }
            }
        }
        __syncthreads();
        {
            int r0 = wm * 16 + (lane >> 2);
            if (kh == 1) {
#pragma unroll
                for (int nt = 0; nt < 2; nt++) {
                    int c = nt * 8 + (lane & 3) * 2;
                    dsm0[c * 132 + r0]           += d0[nt][0];
                    dsm0[(c + 1) * 132 + r0]     += d0[nt][1];
                    dsm0[c * 132 + r0 + 8]       += d0[nt][2];
                    dsm0[(c + 1) * 132 + r0 + 8] += d0[nt][3];
                    dsm1[c * 132 + r0]           += d1[nt][0];
                    dsm1[(c + 1) * 132 + r0]     += d1[nt][1];
                    dsm1[c * 132 + r0 + 8]       += d1[nt][2];
                    dsm1[(c + 1) * 132 + r0 + 8] += d1[nt][3];
                }
            }
        }
        __syncthreads();

        // ---- L0 epilogue: write h0(i) ----
        if (doL0) {
            float gi = dsm0[(0  + u) * 132 + row] + g0v[0];
            float gj = dsm0[(4  + u) * 132 + row] + g0v[1];
            float gf = dsm0[(8  + u) * 132 + row] + g0v[2];
            float go = dsm0[(12 + u) * 132 + row] + g0v[3];
            float cn = c0r * sigm(gf + 1.0f) + sigm(gi) * tanh_(gj);
            c0r = cn;
            float hv = tanh_(cn) * sigm(go);
            unsigned short h16 = bfr(hv);
            *(unsigned short*)(g_h0hi[pW] + eoff) = h16;
            *(unsigned short*)(g_h0lo[pW] + eoff) = bfr(hv - bf2f(h16));
        }
        // ---- L1 epilogue: write h1(i-1) ----
        if (doL1) {
            float gi = dsm1[(0  + u) * 132 + row] + bias1s[0  + u];
            float gj = dsm1[(4  + u) * 132 + row] + bias1s[4  + u];
            float gf = dsm1[(8  + u) * 132 + row] + bias1s[8  + u];
            float go = dsm1[(12 + u) * 132 + row] + bias1s[12 + u];
            float cn = c1r * sigm(gf + 1.0f) + sigm(gi) * tanh_(gj);
            c1r = cn;
            float hv = tanh_(cn) * sigm(go);
            unsigned short h16 = bfr(hv);
            *(unsigned short*)(g_h1hi[pA] + eoff) = h16;
            *(unsigned short*)(g_h1lo[pA] + eoff) = bfr(hv - bf2f(h16));
            if (i == Tt) g_h1f[(cell0 + u) * Bb + row] = hv;
        }
        grid_sync();
    }

    // ---- final logits: CTA = batch row ----
    {
        float s0 = 0.f, s1 = 0.f;
        {
            int n = tid;  // 512 threads = Hh
            float h = __ldcg(&g_h1f[n * Bb + cta]);
            s0 = h * Wd[n * 2];
            s1 = h * Wd[n * 2 + 1];
        }
        float* red = dsm0;
        float* red2 = dsm1;
        red[tid] = s0; red2[tid] = s1;
        __syncthreads();
        for (int st = 256; st > 0; st >>= 1) {
            if (tid < st) {
                red[tid] += red[tid + st];
                red2[tid] += red2[tid + st];
            }
            __syncthreads();
        }
        if (tid == 0) {
            out[cta * 2]     = red[0]  + bd[0];
            out[cta * 2 + 1] = red2[0] + bd[1];
        }
    }
}

// ---------------- launch ----------------
extern "C" void kernel_launch(void* const* d_in, const int* in_sizes, int n_in,
                              void* d_out, int out_size)
{
    const void*  x   = d_in[0];
    const float* emb = (const float*)d_in[1];
    const float* W0  = (const float*)d_in[2];
    const float* b0  = (const float*)d_in[3];
    const float* W1  = (const float*)d_in[4];
    const float* b1  = (const float*)d_in[5];
    const float* Wd  = (const float*)d_in[6];
    const float* bd  = (const float*)d_in[7];
    float* out = (float*)d_out;
    (void)in_sizes; (void)n_in; (void)out_size;

    static int init_done = 0;
    if (!init_done) {
        cudaFuncSetAttribute(lstm_mma, cudaFuncAttributeMaxDynamicSharedMemorySize, SMEM_BYTES);
        init_done = 1;
    }

    detect_kernel<<<1, 1>>>(x);
    reset_kernel<<<1, 1>>>();

    dim3 gp(FH / 64, (Bb * Tt) / 64);
    gemm_in_kernel<<<gp, 256>>>(x, emb, W0, b0);

    lstm_mma<<<NCTA, 512, SMEM_BYTES>>>(W0, W1, b1, Wd, bd, out);
}

// round 9
// speedup vs baseline: 3.7149x; 1.5649x over previous
#include <cuda_runtime.h>
#include <cuda_bf16.h>

#define Bb 128
#define Tt 256
#define Hh 512
#define Ee 300
#define Vv 50000
#define FH 2048
#define NCTA 128

#define SMEM_BYTES 115264
#define W0F_OFF 0
#define W1F_OFF 32768
#define DSM0_OFF 98304
#define DSM1_OFF 106752
#define BIAS_OFF 115200

// ---------------- globals ----------------
__device__ float g_G0in[(size_t)Tt * FH * Bb];   // [t][gatecol][b]
// h planes in A-fragment layout (validated R6/R7):
//   uint4 idx = kt*256 + wm*32 + lane; row=wm*16+(lane>>2), kp=kt*8+(lane&3)
__device__ __align__(16) unsigned char g_h0hi[2][131072];
__device__ __align__(16) unsigned char g_h0lo[2][131072];
__device__ __align__(16) unsigned char g_h1hi[2][131072];
__device__ __align__(16) unsigned char g_h1lo[2][131072];
__device__ float g_h1f[Hh * Bb];
__device__ int g_x64;
__device__ unsigned g_slots[NCTA];
__device__ volatile unsigned g_rel;

// ---------------- helpers ----------------
__device__ __forceinline__ unsigned long long pack2(float lo, float hi) {
    unsigned long long r; asm("mov.b64 %0, {%1, %2};" : "=l"(r) : "f"(lo), "f"(hi)); return r;
}
__device__ __forceinline__ void unpack2(unsigned long long v, float& lo, float& hi) {
    asm("mov.b64 {%0, %1}, %2;" : "=f"(lo), "=f"(hi) : "l"(v));
}
__device__ __forceinline__ unsigned long long fma2(unsigned long long a, unsigned long long b, unsigned long long c) {
    unsigned long long d; asm("fma.rn.f32x2 %0, %1, %2, %3;" : "=l"(d) : "l"(a), "l"(b), "l"(c)); return d;
}
__device__ __forceinline__ float ex2f(float x) { float y; asm("ex2.approx.f32 %0, %1;" : "=f"(y) : "f"(x)); return y; }
__device__ __forceinline__ float rcpf(float x) { float y; asm("rcp.approx.f32 %0, %1;" : "=f"(y) : "f"(x)); return y; }
__device__ __forceinline__ float sigm(float x) { return rcpf(1.0f + ex2f(-1.4426950408889634f * x)); }
__device__ __forceinline__ float tanh_(float x) { return fmaf(2.0f, sigm(2.0f * x), -1.0f); }
__device__ __forceinline__ unsigned short bfr(float f) {
    unsigned short u; asm("cvt.rn.bf16.f32 %0, %1;" : "=h"(u) : "f"(f)); return u;
}
__device__ __forceinline__ float bf2f(unsigned short u) {
    return __uint_as_float((unsigned)u << 16);
}
__device__ __forceinline__ unsigned pkb(float even, float odd) {
    return (unsigned)bfr(even) | ((unsigned)bfr(odd) << 16);
}

__device__ __forceinline__ void mma_bf16(float d[4], const uint4& a, unsigned b0, unsigned b1) {
    asm volatile("mma.sync.aligned.m16n8k16.row.col.f32.bf16.bf16.f32 "
        "{%0,%1,%2,%3}, {%4,%5,%6,%7}, {%8,%9}, {%0,%1,%2,%3};"
        : "+f"(d[0]), "+f"(d[1]), "+f"(d[2]), "+f"(d[3])
        : "r"(a.x), "r"(a.y), "r"(a.z), "r"(a.w), "r"(b0), "r"(b1));
}

// slot barrier: parallel arrivals, CTA0 collects, single release flag
__device__ __forceinline__ void grid_sync(unsigned gen) {
    __syncthreads();
    if (threadIdx.x == 0) {
        __threadfence();
        ((volatile unsigned*)g_slots)[blockIdx.x] = gen;
    }
    if (blockIdx.x == 0) {
        if (threadIdx.x < NCTA) {
            while (((volatile unsigned*)g_slots)[threadIdx.x] < gen) { }
            __threadfence();
        }
        __syncthreads();
        if (threadIdx.x == 0) g_rel = gen;
    } else {
        if (threadIdx.x == 0) {
            while (g_rel < gen) { }
            __threadfence();
        }
    }
    __syncthreads();
}

// ---------------- detect / reset ----------------
__global__ void detect_kernel(const void* x) {
    const long long* p = (const long long*)x;
    int ok64 = 1;
    for (int i = 0; i < 16; i++) { long long v = p[i]; if (v < 0 || v >= Vv) ok64 = 0; }
    g_x64 = ok64;
}
__device__ __forceinline__ int token_at(const void* x, int idx) {
    if (g_x64) return (int)((const long long*)x)[idx];
    return ((const int*)x)[idx];
}
__global__ void reset_kernel() {
    for (int i = 0; i < NCTA; i++) g_slots[i] = 0;
    g_rel = 0;
}

// ---------------- G0in precompute (validated R2) ----------------
__global__ void __launch_bounds__(256) gemm_in_kernel(
    const void* __restrict__ x, const float* __restrict__ emb,
    const float* __restrict__ W0, const float* __restrict__ b0)
{
    __shared__ __align__(16) float As[20][66];
    __shared__ __align__(16) float Bs[20][64];
    __shared__ float Gs[64][65];
    __shared__ int rows[64];

    int tid = threadIdx.x;
    int n0 = blockIdx.x * 64;
    int m0 = blockIdx.y * 64;

    if (tid < 64) {
        int m = m0 + tid;
        rows[tid] = token_at(x, (m & 127) * Tt + (m >> 7));
    }
    __syncthreads();

    int ty = tid >> 4, tx = tid & 15;
    unsigned long long acc[2][4];
#pragma unroll
    for (int i = 0; i < 2; i++)
#pragma unroll
        for (int j = 0; j < 4; j++) acc[i][j] = 0ULL;

    for (int k0 = 0; k0 < Ee; k0 += 20) {
#pragma unroll
        for (int i = 0; i < 5; i++) {
            int idx = i * 256 + tid;
            As[idx >> 6][idx & 63] = emb[rows[idx & 63] * Ee + k0 + (idx >> 6)];
        }
#pragma unroll
        for (int i = 0; i < 5; i++) {
            int idx = i * 256 + tid;
            Bs[idx >> 6][idx & 63] = W0[(k0 + (idx >> 6)) * FH + n0 + (idx & 63)];
        }
        __syncthreads();
#pragma unroll
        for (int kk = 0; kk < 20; kk++) {
            float2 a01 = *(const float2*)&As[kk][ty * 4];
            float2 a23 = *(const float2*)&As[kk][ty * 4 + 2];
            float4 b4  = *(const float4*)&Bs[kk][tx * 4];
            unsigned long long ap0 = pack2(a01.x, a01.y);
            unsigned long long ap1 = pack2(a23.x, a23.y);
            unsigned long long bp;
            bp = pack2(b4.x, b4.x); acc[0][0] = fma2(ap0, bp, acc[0][0]); acc[1][0] = fma2(ap1, bp, acc[1][0]);
            bp = pack2(b4.y, b4.y); acc[0][1] = fma2(ap0, bp, acc[0][1]); acc[1][1] = fma2(ap1, bp, acc[1][1]);
            bp = pack2(b4.z, b4.z); acc[0][2] = fma2(ap0, bp, acc[0][2]); acc[1][2] = fma2(ap1, bp, acc[1][2]);
            bp = pack2(b4.w, b4.w); acc[0][3] = fma2(ap0, bp, acc[0][3]); acc[1][3] = fma2(ap1, bp, acc[1][3]);
        }
        __syncthreads();
    }

#pragma unroll
    for (int j = 0; j < 4; j++) {
        int c = tx * 4 + j;
        float bias = b0[n0 + c];
        float v0, v1, v2, v3;
        unpack2(acc[0][j], v0, v1);
        unpack2(acc[1][j], v2, v3);
        Gs[c][ty * 4 + 0] = v0 + bias;
        Gs[c][ty * 4 + 1] = v1 + bias;
        Gs[c][ty * 4 + 2] = v2 + bias;
        Gs[c][ty * 4 + 3] = v3 + bias;
    }
    __syncthreads();

    int tblk = m0 >> 7, bbase = m0 & 127;
#pragma unroll
    for (int i = 0; i < 16; i++) {
        int e = i * 256 + tid;
        g_G0in[((size_t)tblk * FH + n0 + (e >> 6)) * Bb + bbase + (e & 63)] = Gs[e >> 6][e & 63];
    }
}

// ---------------- persistent warp-MMA LSTM (16 warps, K-split, burst loads) ----------------
__global__ void __launch_bounds__(512, 1) lstm_mma(
    const float* __restrict__ W0, const float* __restrict__ W1,
    const float* __restrict__ b1, const float* __restrict__ Wd,
    const float* __restrict__ bd, float* __restrict__ out)
{
    extern __shared__ char smc[];
    uint4* w0f = (uint4*)(smc + W0F_OFF);   // [kt32][nt2][lane32]
    uint4* w1f = (uint4*)(smc + W1F_OFF);   // [kt64][nt2][lane32]
    float* dsm0 = (float*)(smc + DSM0_OFF); // [col16][132]
    float* dsm1 = (float*)(smc + DSM1_OFF);
    float* bias1s = (float*)(smc + BIAS_OFF);

    const int tid = threadIdx.x;
    const int cta = blockIdx.x;
    const int cell0 = cta * 4;
    const int wid = tid >> 5;
    const int lane = tid & 31;
    const int kh = wid >> 3;
    const int wm = wid & 7;

    // ---- build W fragments (once) ----
    for (int idx = tid; idx < 2048; idx += 512) {
        int kt = idx >> 6, nt = (idx >> 5) & 1, ln = idx & 31;
        int col = nt * 8 + (ln >> 2);
        int gcol = (col >> 2) * 512 + cell0 + (col & 3);
        int kb = kt * 16 + (ln & 3) * 2;
        float v0 = W0[(size_t)(Ee + kb) * FH + gcol];
        float v1 = W0[(size_t)(Ee + kb + 1) * FH + gcol];
        float v8 = W0[(size_t)(Ee + kb + 8) * FH + gcol];
        float v9 = W0[(size_t)(Ee + kb + 9) * FH + gcol];
        unsigned short h0 = bfr(v0), h1 = bfr(v1), h8 = bfr(v8), h9 = bfr(v9);
        w0f[idx] = make_uint4(
            (unsigned)h0 | ((unsigned)h1 << 16),
            (unsigned)h8 | ((unsigned)h9 << 16),
            pkb(v0 - bf2f(h0), v1 - bf2f(h1)),
            pkb(v8 - bf2f(h8), v9 - bf2f(h9)));
    }
    for (int idx = tid; idx < 4096; idx += 512) {
        int kt = idx >> 6, nt = (idx >> 5) & 1, ln = idx & 31;
        int col = nt * 8 + (ln >> 2);
        int gcol = (col >> 2) * 512 + cell0 + (col & 3);
        int kb = kt * 16 + (ln & 3) * 2;
        float v0 = W1[(size_t)kb * FH + gcol];
        float v1 = W1[(size_t)(kb + 1) * FH + gcol];
        float v8 = W1[(size_t)(kb + 8) * FH + gcol];
        float v9 = W1[(size_t)(kb + 9) * FH + gcol];
        unsigned short h0 = bfr(v0), h1 = bfr(v1), h8 = bfr(v8), h9 = bfr(v9);
        w1f[idx] = make_uint4(
            (unsigned)h0 | ((unsigned)h1 << 16),
            (unsigned)h8 | ((unsigned)h9 << 16),
            pkb(v0 - bf2f(h0), v1 - bf2f(h1)),
            pkb(v8 - bf2f(h8), v9 - bf2f(h9)));
    }
    if (tid < 16) bias1s[tid] = b1[(tid >> 2) * 512 + cell0 + (tid & 3)];

    {
        int o = cta * 512 + tid;
        if (o < 8192) {
            uint4 z = make_uint4(0, 0, 0, 0);
            ((uint4*)g_h0hi[1])[o] = z; ((uint4*)g_h0lo[1])[o] = z;
            ((uint4*)g_h1hi[1])[o] = z; ((uint4*)g_h1lo[1])[o] = z;
        }
    }
    unsigned gen = 1;
    grid_sync(gen);

    // epilogue mapping: one cell per thread (validated R7)
    const int row = tid & 127;
    const int u = tid >> 7;
    const int kp_g = (cell0 + u) >> 1;
    const int half = u & 1;
    const int kt_e = kp_g >> 3, kpi = kp_g & 7;
    const int rr = row & 15;
    const unsigned eoff = (unsigned)(kt_e * 4096 + (row >> 4) * 512 +
                          (((rr & 7) << 2) | (kpi & 3)) * 16 +
                          ((kpi >= 4 ? 2 : 0) + (rr >= 8 ? 1 : 0)) * 4 + half * 2);
    float c0r = 0.f, c1r = 0.f;

    const unsigned fbase = wm * 32 + lane;
    const unsigned kbase = kh * 16;

    for (int i = 0; i <= Tt; i++) {
        const int pA = (i + 1) & 1;
        const int pW = i & 1;
        const bool doL0 = (i < Tt);
        const bool doL1 = (i > 0);

        float g0v[4];
        if (doL0) {
#pragma unroll
            for (int g = 0; g < 4; g++)
                g0v[g] = __ldcg(&g_G0in[((size_t)i * FH + g * 512 + cell0 + u) * Bb + row]);
        }

        float d0[2][4], d1[2][4];
#pragma unroll
        for (int n = 0; n < 2; n++)
#pragma unroll
            for (int q = 0; q < 4; q++) { d0[n][q] = 0.f; d1[n][q] = 0.f; }

        // ---- pass 1: A = h0(i-1) K-half; 4-kt bursts, double-buffered ----
        {
            const uint4* ah = (const uint4*)g_h0hi[pA];
            const uint4* al = (const uint4*)g_h0lo[pA];
            uint4 A[2][4], L[2][4];
#pragma unroll
            for (int j = 0; j < 4; j++) {
                A[0][j] = __ldcg(ah + (kbase + j) * 256 + fbase);
                L[0][j] = __ldcg(al + (kbase + j) * 256 + fbase);
            }
#pragma unroll
            for (int kb = 0; kb < 4; kb++) {
                const int cur = kb & 1, nxt = cur ^ 1;
                if (kb < 3) {
#pragma unroll
                    for (int j = 0; j < 4; j++) {
                        A[nxt][j] = __ldcg(ah + (kbase + (kb + 1) * 4 + j) * 256 + fbase);
                        L[nxt][j] = __ldcg(al + (kbase + (kb + 1) * 4 + j) * 256 + fbase);
                    }
                }
#pragma unroll
                for (int j = 0; j < 4; j++) {
                    const int kt = kbase + kb * 4 + j;
#pragma unroll
                    for (int nt = 0; nt < 2; nt++) {
                        if (doL0) {
                            uint4 w = w0f[(kt * 2 + nt) * 32 + lane];
                            mma_bf16(d0[nt], A[cur][j], w.x, w.y);
                            mma_bf16(d0[nt], L[cur][j], w.x, w.y);
                            mma_bf16(d0[nt], A[cur][j], w.z, w.w);
                        }
                        if (doL1) {
                            uint4 w = w1f[(kt * 2 + nt) * 32 + lane];
                            mma_bf16(d1[nt], A[cur][j], w.x, w.y);
                            mma_bf16(d1[nt], L[cur][j], w.x, w.y);
                            mma_bf16(d1[nt], A[cur][j], w.z, w.w);
                        }
                    }
                }
            }
        }
        // ---- pass 2: A = h1(i-2) K-half; W1 rows 512..1023 ----
        if (doL1) {
            const uint4* ah = (const uint4*)g_h1hi[pW];
            const uint4* al = (const uint4*)g_h1lo[pW];
            uint4 A[2][4], L[2][4];
#pragma unroll
            for (int j = 0; j < 4; j++) {
                A[0][j] = __ldcg(ah + (kbase + j) * 256 + fbase);
                L[0][j] = __ldcg(al + (kbase + j) * 256 + fbase);
            }
#pragma unroll
            for (int kb = 0; kb < 4; kb++) {
                const int cur = kb & 1, nxt = cur ^ 1;
                if (kb < 3) {
#pragma unroll
                    for (int j = 0; j < 4; j++) {
                        A[nxt][j] = __ldcg(ah + (kbase + (kb + 1) * 4 + j) * 256 + fbase);
                        L[nxt][j] = __ldcg(al + (kbase + (kb + 1) * 4 + j) * 256 + fbase);
                    }
                }
#pragma unroll
                for (int j = 0; j < 4; j++) {
                    const int kt = kbase + kb * 4 + j;
#pragma unroll
                    for (int nt = 0; nt < 2; nt++) {
                        uint4 w = w1f[((32 + kt) * 2 + nt) * 32 + lane];
                        mma_bf16(d1[nt], A[cur][j], w.x, w.y);
                        mma_bf16(d1[nt], L[cur][j], w.x, w.y);
                        mma_bf16(d1[nt], A[cur][j], w.z, w.w);
                    }
                }
            }
        }

        // ---- combine K-halves in SMEM: kh=0 stores, kh=1 adds (validated R7) ----
        __syncthreads();
        {
            int r0 = wm * 16 + (lane >> 2);
            if (kh == 0) {
#pragma unroll
                for (int nt = 0; nt < 2; nt++) {
                    int c = nt * 8 + (lane & 3) * 2;
                    dsm0[c * 132 + r0]           = d0[nt][0];
                    dsm0[(c + 1) * 132 + r0]     = d0[nt][1];
                    dsm0[c * 132 + r0 + 8]       = d0[nt][2];
                    dsm0[(c + 1) * 132 + r0 + 8] = d0[nt][3];
                    dsm1[c * 132 + r0]           = d1[nt][0];
                    dsm1[(c + 1) * 132 + r0]     = d1[nt][1];
                    dsm1[c * 132 + r0 + 8]       = d1[nt][2];
                    dsm1[(c + 1) * 132 + r0 + 8] = d1[nt][3];
                }
            }
        }
        __syncthreads();
        {
            int r0 = wm * 16 + (lane >> 2);
            if (kh == 1) {
#pragma unroll
                for (int nt = 0; nt < 2; nt++) {
                    int c = nt * 8 + (lane & 3) * 2;
                    dsm0[c * 132 + r0]           += d0[nt][0];
                    dsm0[(c + 1) * 132 + r0]     += d0[nt][1];
                    dsm0[c * 132 + r0 + 8]       += d0[nt][2];
                    dsm0[(c + 1) * 132 + r0 + 8] += d0[nt][3];
                    dsm1[c * 132 + r0]           += d1[nt][0];
                    dsm1[(c + 1) * 132 + r0]     += d1[nt][1];
                    dsm1[c * 132 + r0 + 8]       += d1[nt][2];
                    dsm1[(c + 1) * 132 + r0 + 8] += d1[nt][3];
                }
            }
        }
        __syncthreads();

        // ---- L0 epilogue: write h0(i) ----
        if (doL0) {
            float gi = dsm0[(0  + u) * 132 + row] + g0v[0];
            float gj = dsm0[(4  + u) * 132 + row] + g0v[1];
            float gf = dsm0[(8  + u) * 132 + row] + g0v[2];
            float go = dsm0[(12 + u) * 132 + row] + g0v[3];
            float cn = c0r * sigm(gf + 1.0f) + sigm(gi) * tanh_(gj);
            c0r = cn;
            float hv = tanh_(cn) * sigm(go);
            unsigned short h16 = bfr(hv);
            *(unsigned short*)(g_h0hi[pW] + eoff) = h16;
            *(unsigned short*)(g_h0lo[pW] + eoff) = bfr(hv - bf2f(h16));
        }
        // ---- L1 epilogue: write h1(i-1) ----
        if (doL1) {
            float gi = dsm1[(0  + u) * 132 + row] + bias1s[0  + u];
            float gj = dsm1[(4  + u) * 132 + row] + bias1s[4  + u];
            float gf = dsm1[(8  + u) * 132 + row] + bias1s[8  + u];
            float go = dsm1[(12 + u) * 132 + row] + bias1s[12 + u];
            float cn = c1r * sigm(gf + 1.0f) + sigm(gi) * tanh_(gj);
            c1r = cn;
            float hv = tanh_(cn) * sigm(go);
            unsigned short h16 = bfr(hv);
            *(unsigned short*)(g_h1hi[pA] + eoff) = h16;
            *(unsigned short*)(g_h1lo[pA] + eoff) = bfr(hv - bf2f(h16));
            if (i == Tt) g_h1f[(cell0 + u) * Bb + row] = hv;
        }
        gen++;
        grid_sync(gen);
    }

    // ---- final logits: CTA = batch row ----
    {
        float s0 = 0.f, s1 = 0.f;
        {
            int n = tid;
            float h = __ldcg(&g_h1f[n * Bb + cta]);
            s0 = h * Wd[n * 2];
            s1 = h * Wd[n * 2 + 1];
        }
        float* red = dsm0;
        float* red2 = dsm1;
        red[tid] = s0; red2[tid] = s1;
        __syncthreads();
        for (int st = 256; st > 0; st >>= 1) {
            if (tid < st) {
                red[tid] += red[tid + st];
                red2[tid] += red2[tid + st];
            }
            __syncthreads();
        }
        if (tid == 0) {
            out[cta * 2]     = red[0]  + bd[0];
            out[cta * 2 + 1] = red2[0] + bd[1];
        }
    }
}

// ---------------- launch ----------------
extern "C" void kernel_launch(void* const* d_in, const int* in_sizes, int n_in,
                              void* d_out, int out_size)
{
    const void*  x   = d_in[0];
    const float* emb = (const float*)d_in[1];
    const float* W0  = (const float*)d_in[2];
    const float* b0  = (const float*)d_in[3];
    const float* W1  = (const float*)d_in[4];
    const float* b1  = (const float*)d_in[5];
    const float* Wd  = (const float*)d_in[6];
    const float* bd  = (const float*)d_in[7];
    float* out = (float*)d_out;
    (void)in_sizes; (void)n_in; (void)out_size;

    static int init_done = 0;
    if (!init_done) {
        cudaFuncSetAttribute(lstm_mma, cudaFuncAttributeMaxDynamicSharedMemorySize, SMEM_BYTES);
        init_done = 1;
    }

    detect_kernel<<<1, 1>>>(x);
    reset_kernel<<<1, 1>>>();

    dim3 gp(FH / 64, (Bb * Tt) / 64);
    gemm_in_kernel<<<gp, 256>>>(x, emb, W0, b0);

    lstm_mma<<<NCTA, 512, SMEM_BYTES>>>(W0, W1, b1, Wd, bd, out);
}

// round 10
// speedup vs baseline: 4.3660x; 1.1753x over previous
#include <cuda_runtime.h>
#include <cuda_bf16.h>

#define Bb 128
#define Tt 256
#define Hh 512
#define Ee 300
#define Vv 50000
#define FH 2048
#define NCTA 128

// lstm smem offsets
#define W0F_OFF 0
#define W1F_OFF 32768
#define DSM0_OFF 98304
#define DSM1_OFF 106752
#define DSM0B_OFF 115264
#define DSM1B_OFF 123712
#define BIAS_OFF 132160
#define SMEM_BYTES 132224

// gemm_in smem offsets
#define GI_ROWS_OFF 0
#define GI_WF_OFF 1024
#define GI_DSM_OFF 66560
#define GI_SMEM_BYTES 100352

// ---------------- globals ----------------
__device__ float g_G0in[(size_t)Tt * FH * Bb];   // [t][gatecol][b]
// h planes in A-fragment layout (validated R6/R7):
//   uint4 idx = kt*256 + wm*32 + lane; row=wm*16+(lane>>2), kp=kt*8+(lane&3)
__device__ __align__(16) unsigned char g_h0hi[2][131072];
__device__ __align__(16) unsigned char g_h0lo[2][131072];
__device__ __align__(16) unsigned char g_h1hi[2][131072];
__device__ __align__(16) unsigned char g_h1lo[2][131072];
__device__ float g_h1f[Hh * Bb];
__device__ int g_x64;
__device__ unsigned g_slots[NCTA];
__device__ volatile unsigned g_rel;

// ---------------- helpers ----------------
__device__ __forceinline__ float ex2f(float x) { float y; asm("ex2.approx.f32 %0, %1;" : "=f"(y) : "f"(x)); return y; }
__device__ __forceinline__ float rcpf(float x) { float y; asm("rcp.approx.f32 %0, %1;" : "=f"(y) : "f"(x)); return y; }
__device__ __forceinline__ float sigm(float x) { return rcpf(1.0f + ex2f(-1.4426950408889634f * x)); }
__device__ __forceinline__ float tanh_(float x) { return fmaf(2.0f, sigm(2.0f * x), -1.0f); }
__device__ __forceinline__ unsigned short bfr(float f) {
    unsigned short u; asm("cvt.rn.bf16.f32 %0, %1;" : "=h"(u) : "f"(f)); return u;
}
__device__ __forceinline__ float bf2f(unsigned short u) {
    return __uint_as_float((unsigned)u << 16);
}
__device__ __forceinline__ unsigned pkb(float even, float odd) {
    return (unsigned)bfr(even) | ((unsigned)bfr(odd) << 16);
}
// split two floats into packed-bf16 hi and lo planes
__device__ __forceinline__ void split2(float a, float b, unsigned& hi, unsigned& lo) {
    unsigned short ha = bfr(a), hb = bfr(b);
    hi = (unsigned)ha | ((unsigned)hb << 16);
    lo = (unsigned)bfr(a - bf2f(ha)) | ((unsigned)bfr(b - bf2f(hb)) << 16);
}

__device__ __forceinline__ void mma_bf16(float d[4], const uint4& a, unsigned b0, unsigned b1) {
    asm volatile("mma.sync.aligned.m16n8k16.row.col.f32.bf16.bf16.f32 "
        "{%0,%1,%2,%3}, {%4,%5,%6,%7}, {%8,%9}, {%0,%1,%2,%3};"
        : "+f"(d[0]), "+f"(d[1]), "+f"(d[2]), "+f"(d[3])
        : "r"(a.x), "r"(a.y), "r"(a.z), "r"(a.w), "r"(b0), "r"(b1));
}

// slot barrier (validated R8)
__device__ __forceinline__ void grid_sync(unsigned gen) {
    __syncthreads();
    if (threadIdx.x == 0) {
        __threadfence();
        ((volatile unsigned*)g_slots)[blockIdx.x] = gen;
    }
    if (blockIdx.x == 0) {
        if (threadIdx.x < NCTA) {
            while (((volatile unsigned*)g_slots)[threadIdx.x] < gen) { }
            __threadfence();
        }
        __syncthreads();
        if (threadIdx.x == 0) g_rel = gen;
    } else {
        if (threadIdx.x == 0) {
            while (g_rel < gen) { }
            __threadfence();
        }
    }
    __syncthreads();
}

// ---------------- detect / reset ----------------
__global__ void detect_kernel(const void* x) {
    const long long* p = (const long long*)x;
    int ok64 = 1;
    for (int i = 0; i < 16; i++) { long long v = p[i]; if (v < 0 || v >= Vv) ok64 = 0; }
    g_x64 = ok64;
}
__device__ __forceinline__ int token_at(const void* x, int idx) {
    if (g_x64) return (int)((const long long*)x)[idx];
    return ((const int*)x)[idx];
}
__global__ void reset_kernel() {
    for (int i = 0; i < NCTA; i++) g_slots[i] = 0;
    g_rel = 0;
}

// ---------------- G0in precompute: warp-MMA bf16 3-term ----------------
// grid (16 ntile, 256 t), 512 threads. CTA computes G0in[t][bx*128 .. +127][all 128 b].
// K = 300 -> 19 k16 tiles, zero-padded.
__global__ void __launch_bounds__(512) gemm_in_mma(
    const void* __restrict__ x, const float* __restrict__ emb,
    const float* __restrict__ W0, const float* __restrict__ b0)
{
    extern __shared__ char smg[];
    int* rows = (int*)(smg + GI_ROWS_OFF);
    uint4* wf = (uint4*)(smg + GI_WF_OFF);       // 2 bufs x [j4][cg16][lane32]
    float* dsmA = (float*)(smg + GI_DSM_OFF);            // [32col][132]
    float* dsmB = (float*)(smg + GI_DSM_OFF + 16896);

    const int tid = threadIdx.x;
    const int bx = blockIdx.x;
    const int t = blockIdx.y;
    const int wid = tid >> 5;
    const int lane = tid & 31;
    const int wm = wid & 7;
    const int nh = wid >> 3;

    if (tid < 128) rows[tid] = token_at(x, tid * Tt + t);

    // W frag builder for chunk kc into buffer buf (mirrors validated lstm w-builder)
    auto build_w = [&](int kc, int buf) {
        int nkt = (kc == 4) ? 3 : 4;
        uint4* dst = wf + buf * 2048;
        for (int e = tid; e < nkt * 512; e += 512) {
            int j = e >> 9, cg = (e >> 5) & 15, ln = e & 31;
            int col = bx * 128 + cg * 8 + (ln >> 2);
            int k = (kc * 4 + j) * 16 + (ln & 3) * 2;
            float v0 = (k     < Ee) ? W0[(size_t)k * FH + col]       : 0.f;
            float v1 = (k + 1 < Ee) ? W0[(size_t)(k + 1) * FH + col] : 0.f;
            float v8 = (k + 8 < Ee) ? W0[(size_t)(k + 8) * FH + col] : 0.f;
            float v9 = (k + 9 < Ee) ? W0[(size_t)(k + 9) * FH + col] : 0.f;
            unsigned h01, l01, h89, l89;
            split2(v0, v1, h01, l01);
            split2(v8, v9, h89, l89);
            dst[(j * 16 + cg) * 32 + ln] = make_uint4(h01, h89, l01, l89);
        }
    };

    __syncthreads();   // rows visible
    build_w(0, 0);
    __syncthreads();

    float d[8][4];
#pragma unroll
    for (int n = 0; n < 8; n++)
#pragma unroll
        for (int q = 0; q < 4; q++) d[n][q] = 0.f;

    const int r1 = wm * 16 + (lane >> 2);
    const int r2 = r1 + 8;
    const float* e1 = emb + (size_t)rows[r1] * Ee;
    const float* e2 = emb + (size_t)rows[r2] * Ee;

    for (int kc = 0; kc < 5; kc++) {
        int nkt = (kc == 4) ? 3 : 4;
        // gather A fragments for this chunk (hi + lo planes)
        uint4 Ah[4], Al[4];
        for (int j = 0; j < nkt; j++) {
            int k = (kc * 4 + j) * 16 + (lane & 3) * 2;
            float a0 = (k     < Ee) ? e1[k]     : 0.f;
            float a1 = (k + 1 < Ee) ? e1[k + 1] : 0.f;
            float b0v = (k     < Ee) ? e2[k]     : 0.f;
            float b1v = (k + 1 < Ee) ? e2[k + 1] : 0.f;
            float c0 = (k + 8 < Ee) ? e1[k + 8] : 0.f;
            float c1 = (k + 9 < Ee) ? e1[k + 9] : 0.f;
            float f0 = (k + 8 < Ee) ? e2[k + 8] : 0.f;
            float f1 = (k + 9 < Ee) ? e2[k + 9] : 0.f;
            unsigned xh, xl, yh, yl, zh, zl, wh, wl;
            split2(a0, a1, xh, xl);
            split2(b0v, b1v, yh, yl);
            split2(c0, c1, zh, zl);
            split2(f0, f1, wh, wl);
            Ah[j] = make_uint4(xh, yh, zh, wh);
            Al[j] = make_uint4(xl, yl, zl, wl);
        }
        const uint4* wcur = wf + (kc & 1) * 2048;
        for (int j = 0; j < nkt; j++) {
#pragma unroll
            for (int nt = 0; nt < 8; nt++) {
                uint4 w = wcur[(j * 16 + nh * 8 + nt) * 32 + lane];
                mma_bf16(d[nt], Ah[j], w.x, w.y);
                mma_bf16(d[nt], Al[j], w.x, w.y);
                mma_bf16(d[nt], Ah[j], w.z, w.w);
            }
        }
        if (kc < 4) build_w(kc + 1, (kc + 1) & 1);
        __syncthreads();
    }

    // epilogue: two 64-col passes through SMEM transpose, coalesced stores
    const int r0 = wm * 16 + (lane >> 2);
    for (int p = 0; p < 2; p++) {
        float* mybuf = nh ? dsmB : dsmA;
#pragma unroll
        for (int q = 0; q < 4; q++) {
            int nt = p * 4 + q;
            int lc = q * 8 + (lane & 3) * 2;
            mybuf[lc * 132 + r0]           = d[nt][0];
            mybuf[(lc + 1) * 132 + r0]     = d[nt][1];
            mybuf[lc * 132 + r0 + 8]       = d[nt][2];
            mybuf[(lc + 1) * 132 + r0 + 8] = d[nt][3];
        }
        __syncthreads();
#pragma unroll
        for (int it = 0; it < 16; it++) {
            int e = it * 512 + tid;
            int col64 = e >> 7, row = e & 127;
            int half = col64 >> 5, c5 = col64 & 31;
            int gcol = bx * 128 + half * 64 + p * 32 + c5;
            float v = (half ? dsmB : dsmA)[c5 * 132 + row] + b0[gcol];
            g_G0in[((size_t)t * FH + gcol) * Bb + row] = v;
        }
        __syncthreads();
    }
}

// ---------------- persistent warp-MMA LSTM ----------------
__global__ void __launch_bounds__(512, 1) lstm_mma(
    const float* __restrict__ W0, const float* __restrict__ W1,
    const float* __restrict__ b1, const float* __restrict__ Wd,
    const float* __restrict__ bd, float* __restrict__ out)
{
    extern __shared__ char smc[];
    uint4* w0f = (uint4*)(smc + W0F_OFF);
    uint4* w1f = (uint4*)(smc + W1F_OFF);
    float* dsm0 = (float*)(smc + DSM0_OFF);
    float* dsm1 = (float*)(smc + DSM1_OFF);
    float* dsm0b = (float*)(smc + DSM0B_OFF);
    float* dsm1b = (float*)(smc + DSM1B_OFF);
    float* bias1s = (float*)(smc + BIAS_OFF);

    const int tid = threadIdx.x;
    const int cta = blockIdx.x;
    const int cell0 = cta * 4;
    const int wid = tid >> 5;
    const int lane = tid & 31;
    const int kh = wid >> 3;
    const int wm = wid & 7;

    // ---- build W fragments (once; validated) ----
    for (int idx = tid; idx < 2048; idx += 512) {
        int kt = idx >> 6, nt = (idx >> 5) & 1, ln = idx & 31;
        int col = nt * 8 + (ln >> 2);
        int gcol = (col >> 2) * 512 + cell0 + (col & 3);
        int kb = kt * 16 + (ln & 3) * 2;
        float v0 = W0[(size_t)(Ee + kb) * FH + gcol];
        float v1 = W0[(size_t)(Ee + kb + 1) * FH + gcol];
        float v8 = W0[(size_t)(Ee + kb + 8) * FH + gcol];
        float v9 = W0[(size_t)(Ee + kb + 9) * FH + gcol];
        unsigned h01, l01, h89, l89;
        split2(v0, v1, h01, l01);
        split2(v8, v9, h89, l89);
        w0f[idx] = make_uint4(h01, h89, l01, l89);
    }
    for (int idx = tid; idx < 4096; idx += 512) {
        int kt = idx >> 6, nt = (idx >> 5) & 1, ln = idx & 31;
        int col = nt * 8 + (ln >> 2);
        int gcol = (col >> 2) * 512 + cell0 + (col & 3);
        int kb = kt * 16 + (ln & 3) * 2;
        float v0 = W1[(size_t)kb * FH + gcol];
        float v1 = W1[(size_t)(kb + 1) * FH + gcol];
        float v8 = W1[(size_t)(kb + 8) * FH + gcol];
        float v9 = W1[(size_t)(kb + 9) * FH + gcol];
        unsigned h01, l01, h89, l89;
        split2(v0, v1, h01, l01);
        split2(v8, v9, h89, l89);
        w1f[idx] = make_uint4(h01, h89, l01, l89);
    }
    if (tid < 16) bias1s[tid] = b1[(tid >> 2) * 512 + cell0 + (tid & 3)];

    {
        int o = cta * 512 + tid;
        if (o < 8192) {
            uint4 z = make_uint4(0, 0, 0, 0);
            ((uint4*)g_h0hi[1])[o] = z; ((uint4*)g_h0lo[1])[o] = z;
            ((uint4*)g_h1hi[1])[o] = z; ((uint4*)g_h1lo[1])[o] = z;
        }
    }
    unsigned gen = 1;
    grid_sync(gen);

    // epilogue mapping (validated R7)
    const int row = tid & 127;
    const int u = tid >> 7;
    const int kp_g = (cell0 + u) >> 1;
    const int half = u & 1;
    const int kt_e = kp_g >> 3, kpi = kp_g & 7;
    const int rr = row & 15;
    const unsigned eoff = (unsigned)(kt_e * 4096 + (row >> 4) * 512 +
                          (((rr & 7) << 2) | (kpi & 3)) * 16 +
                          ((kpi >= 4 ? 2 : 0) + (rr >= 8 ? 1 : 0)) * 4 + half * 2);
    float c0r = 0.f, c1r = 0.f;

    const unsigned fbase = wm * 32 + lane;
    const unsigned kbase = kh * 16;

    for (int i = 0; i <= Tt; i++) {
        const int pA = (i + 1) & 1;
        const int pW = i & 1;
        const bool doL0 = (i < Tt);
        const bool doL1 = (i > 0);

        float g0v[4];
        if (doL0) {
#pragma unroll
            for (int g = 0; g < 4; g++)
                g0v[g] = __ldcg(&g_G0in[((size_t)i * FH + g * 512 + cell0 + u) * Bb + row]);
        }

        float d0[2][4], d1[2][4];
#pragma unroll
        for (int n = 0; n < 2; n++)
#pragma unroll
            for (int q = 0; q < 4; q++) { d0[n][q] = 0.f; d1[n][q] = 0.f; }

        // ---- pass 1: A = h0(i-1) K-half; 4-kt bursts (validated R8) ----
        {
            const uint4* ah = (const uint4*)g_h0hi[pA];
            const uint4* al = (const uint4*)g_h0lo[pA];
            uint4 A[2][4], L[2][4];
#pragma unroll
            for (int j = 0; j < 4; j++) {
                A[0][j] = __ldcg(ah + (kbase + j) * 256 + fbase);
                L[0][j] = __ldcg(al + (kbase + j) * 256 + fbase);
            }
#pragma unroll
            for (int kb = 0; kb < 4; kb++) {
                const int cur = kb & 1, nxt = cur ^ 1;
                if (kb < 3) {
#pragma unroll
                    for (int j = 0; j < 4; j++) {
                        A[nxt][j] = __ldcg(ah + (kbase + (kb + 1) * 4 + j) * 256 + fbase);
                        L[nxt][j] = __ldcg(al + (kbase + (kb + 1) * 4 + j) * 256 + fbase);
                    }
                }
#pragma unroll
                for (int j = 0; j < 4; j++) {
                    const int kt = kbase + kb * 4 + j;
#pragma unroll
                    for (int nt = 0; nt < 2; nt++) {
                        if (doL0) {
                            uint4 w = w0f[(kt * 2 + nt) * 32 + lane];
                            mma_bf16(d0[nt], A[cur][j], w.x, w.y);
                            mma_bf16(d0[nt], L[cur][j], w.x, w.y);
                            mma_bf16(d0[nt], A[cur][j], w.z, w.w);
                        }
                        if (doL1) {
                            uint4 w = w1f[(kt * 2 + nt) * 32 + lane];
                            mma_bf16(d1[nt], A[cur][j], w.x, w.y);
                            mma_bf16(d1[nt], L[cur][j], w.x, w.y);
                            mma_bf16(d1[nt], A[cur][j], w.z, w.w);
                        }
                    }
                }
            }
        }
        // ---- pass 2: A = h1(i-2) K-half ----
        if (doL1) {
            const uint4* ah = (const uint4*)g_h1hi[pW];
            const uint4* al = (const uint4*)g_h1lo[pW];
            uint4 A[2][4], L[2][4];
#pragma unroll
            for (int j = 0; j < 4; j++) {
                A[0][j] = __ldcg(ah + (kbase + j) * 256 + fbase);
                L[0][j] = __ldcg(al + (kbase + j) * 256 + fbase);
            }
#pragma unroll
            for (int kb = 0; kb < 4; kb++) {
                const int cur = kb & 1, nxt = cur ^ 1;
                if (kb < 3) {
#pragma unroll
                    for (int j = 0; j < 4; j++) {
                        A[nxt][j] = __ldcg(ah + (kbase + (kb + 1) * 4 + j) * 256 + fbase);
                        L[nxt][j] = __ldcg(al + (kbase + (kb + 1) * 4 + j) * 256 + fbase);
                    }
                }
#pragma unroll
                for (int j = 0; j < 4; j++) {
                    const int kt = kbase + kb * 4 + j;
#pragma unroll
                    for (int nt = 0; nt < 2; nt++) {
                        uint4 w = w1f[((32 + kt) * 2 + nt) * 32 + lane];
                        mma_bf16(d1[nt], A[cur][j], w.x, w.y);
                        mma_bf16(d1[nt], L[cur][j], w.x, w.y);
                        mma_bf16(d1[nt], A[cur][j], w.z, w.w);
                    }
                }
            }
        }

        // ---- combine: each K-half writes its OWN buffers; ONE sync ----
        {
            int r0 = wm * 16 + (lane >> 2);
            float* b0p = kh ? dsm0b : dsm0;
            float* b1p = kh ? dsm1b : dsm1;
#pragma unroll
            for (int nt = 0; nt < 2; nt++) {
                int c = nt * 8 + (lane & 3) * 2;
                b0p[c * 132 + r0]           = d0[nt][0];
                b0p[(c + 1) * 132 + r0]     = d0[nt][1];
                b0p[c * 132 + r0 + 8]       = d0[nt][2];
                b0p[(c + 1) * 132 + r0 + 8] = d0[nt][3];
                b1p[c * 132 + r0]           = d1[nt][0];
                b1p[(c + 1) * 132 + r0]     = d1[nt][1];
                b1p[c * 132 + r0 + 8]       = d1[nt][2];
                b1p[(c + 1) * 132 + r0 + 8] = d1[nt][3];
            }
        }
        __syncthreads();

        // ---- L0 epilogue ----
        if (doL0) {
            float gi = dsm0[(0  + u) * 132 + row] + dsm0b[(0  + u) * 132 + row] + g0v[0];
            float gj = dsm0[(4  + u) * 132 + row] + dsm0b[(4  + u) * 132 + row] + g0v[1];
            float gf = dsm0[(8  + u) * 132 + row] + dsm0b[(8  + u) * 132 + row] + g0v[2];
            float go = dsm0[(12 + u) * 132 + row] + dsm0b[(12 + u) * 132 + row] + g0v[3];
            float cn = c0r * sigm(gf + 1.0f) + sigm(gi) * tanh_(gj);
            c0r = cn;
            float hv = tanh_(cn) * sigm(go);
            unsigned short h16 = bfr(hv);
            *(unsigned short*)(g_h0hi[pW] + eoff) = h16;
            *(unsigned short*)(g_h0lo[pW] + eoff) = bfr(hv - bf2f(h16));
        }
        // ---- L1 epilogue ----
        if (doL1) {
            float gi = dsm1[(0  + u) * 132 + row] + dsm1b[(0  + u) * 132 + row] + bias1s[0  + u];
            float gj = dsm1[(4  + u) * 132 + row] + dsm1b[(4  + u) * 132 + row] + bias1s[4  + u];
            float gf = dsm1[(8  + u) * 132 + row] + dsm1b[(8  + u) * 132 + row] + bias1s[8  + u];
            float go = dsm1[(12 + u) * 132 + row] + dsm1b[(12 + u) * 132 + row] + bias1s[12 + u];
            float cn = c1r * sigm(gf + 1.0f) + sigm(gi) * tanh_(gj);
            c1r = cn;
            float hv = tanh_(cn) * sigm(go);
            unsigned short h16 = bfr(hv);
            *(unsigned short*)(g_h1hi[pA] + eoff) = h16;
            *(unsigned short*)(g_h1lo[pA] + eoff) = bfr(hv - bf2f(h16));
            if (i == Tt) g_h1f[(cell0 + u) * Bb + row] = hv;
        }
        gen++;
        grid_sync(gen);
    }

    // ---- final logits ----
    {
        float s0 = 0.f, s1 = 0.f;
        {
            int n = tid;
            float h = __ldcg(&g_h1f[n * Bb + cta]);
            s0 = h * Wd[n * 2];
            s1 = h * Wd[n * 2 + 1];
        }
        float* red = dsm0;
        float* red2 = dsm1;
        red[tid] = s0; red2[tid] = s1;
        __syncthreads();
        for (int st = 256; st > 0; st >>= 1) {
            if (tid < st) {
                red[tid] += red[tid + st];
                red2[tid] += red2[tid + st];
            }
            __syncthreads();
        }
        if (tid == 0) {
            out[cta * 2]     = red[0]  + bd[0];
            out[cta * 2 + 1] = red2[0] + bd[1];
        }
    }
}

// ---------------- launch ----------------
extern "C" void kernel_launch(void* const* d_in, const int* in_sizes, int n_in,
                              void* d_out, int out_size)
{
    const void*  x   = d_in[0];
    const float* emb = (const float*)d_in[1];
    const float* W0  = (const float*)d_in[2];
    const float* b0  = (const float*)d_in[3];
    const float* W1  = (const float*)d_in[4];
    const float* b1  = (const float*)d_in[5];
    const float* Wd  = (const float*)d_in[6];
    const float* bd  = (const float*)d_in[7];
    float* out = (float*)d_out;
    (void)in_sizes; (void)n_in; (void)out_size;

    static int init_done = 0;
    if (!init_done) {
        cudaFuncSetAttribute(lstm_mma, cudaFuncAttributeMaxDynamicSharedMemorySize, SMEM_BYTES);
        cudaFuncSetAttribute(gemm_in_mma, cudaFuncAttributeMaxDynamicSharedMemorySize, GI_SMEM_BYTES);
        init_done = 1;
    }

    detect_kernel<<<1, 1>>>(x);
    reset_kernel<<<1, 1>>>();

    gemm_in_mma<<<dim3(16, 256), 512, GI_SMEM_BYTES>>>(x, emb, W0, b0);

    lstm_mma<<<NCTA, 512, SMEM_BYTES>>>(W0, W1, b1, Wd, bd, out);
}